// round 1
// baseline (speedup 1.0000x reference)
#include <cuda_runtime.h>

#define BB 16
#define SS 4096
#define DD 64
#define KPP 256
#define SCHUNKS 8
#define SCH (SS / SCHUNKS) /* 512 */
#define SCALE 0.125f       /* 1/sqrt(64) */

// Scratch (device globals; no allocation in kernel_launch).
__device__ float g_part[SCHUNKS * 32 * DD * KPP]; // [chunk][proj*16+b][d*256+k]  (16 MB)
__device__ float g_Kp[BB * DD * KPP];             // [b][d][k]
__device__ float g_Vp[BB * KPP * DD];             // [b][k][d]

// ---------- packed fp32x2 helpers (Blackwell sm_103a FFMA2) ----------
__device__ __forceinline__ unsigned long long f2fma(unsigned long long a,
                                                    unsigned long long b,
                                                    unsigned long long c) {
    unsigned long long d_;
    asm("fma.rn.f32x2 %0, %1, %2, %3;" : "=l"(d_) : "l"(a), "l"(b), "l"(c));
    return d_;
}
__device__ __forceinline__ unsigned long long f2dup(float x) {
    unsigned long long d_;
    asm("mov.b64 %0, {%1, %1};" : "=l"(d_) : "f"(x));
    return d_;
}
__device__ __forceinline__ unsigned long long f2pack(float lo, float hi) {
    unsigned long long d_;
    asm("mov.b64 %0, {%1, %2};" : "=l"(d_) : "f"(lo), "f"(hi));
    return d_;
}
__device__ __forceinline__ float2 f2unpack(unsigned long long v) {
    float lo, hi;
    asm("mov.b64 {%0, %1}, %2;" : "=f"(lo), "=f"(hi) : "l"(v));
    return make_float2(lo, hi);
}

// ======================================================================
// Kernel 1: partial projections.
//   C[d][k] = sum_{s in chunk} X[s][d] * W[k][s]
//   proj=0: X=K, W=E_w  -> partial of Kp[b][d][k]
//   proj=1: X=V, W=F_w  -> partial of Vp (stored [d][k]; transposed in reduce)
// grid (SCHUNKS, 16, 2), 256 threads. Per-thread tile: 8d x 8k (f32x2 over d).
// ======================================================================
__global__ __launch_bounds__(256) void proj_partial(const float* __restrict__ Kin,
                                                    const float* __restrict__ Vin,
                                                    const float* __restrict__ Ew,
                                                    const float* __restrict__ Fw) {
    __shared__ __align__(16) float Xs[32][64];   // [s][d]
    __shared__ __align__(16) float Wt[32][257];  // [s][k] padded
    const int tid = threadIdx.x;
    const int chunk = blockIdx.x, b = blockIdx.y, proj = blockIdx.z;

    const float* X = (proj ? Vin : Kin) + ((size_t)b * SS + (size_t)chunk * SCH) * DD;
    const float* W = (proj ? Fw : Ew) + (size_t)chunk * SCH;

    const int ty = tid >> 5;      // 0..7 -> d group of 8
    const int tx = tid & 31;      // k = tx + 32*j
    const int d0 = ty * 8;

    unsigned long long acc[4][8];
#pragma unroll
    for (int i = 0; i < 4; ++i)
#pragma unroll
        for (int j = 0; j < 8; ++j) acc[i][j] = 0ULL;

    for (int t = 0; t < SCH / 32; ++t) {
        // --- load X tile: 32 rows x 64 floats ---
#pragma unroll
        for (int i = 0; i < 2; ++i) {
            int slot = tid + 256 * i;            // 512 float4 slots
            int r = slot >> 4, c4 = slot & 15;
            float4 v = *(const float4*)&X[(size_t)(t * 32 + r) * DD + c4 * 4];
            *(float4*)&Xs[r][c4 * 4] = v;
        }
        // --- load W tile transposed: Wt[s][k], 256 k x 32 s ---
#pragma unroll
        for (int i = 0; i < 8; ++i) {
            int slot = tid + 256 * i;            // 2048 float4 slots
            int k = slot >> 3, f = slot & 7;
            float4 v = *(const float4*)&W[(size_t)k * SS + t * 32 + f * 4];
            Wt[f * 4 + 0][k] = v.x;
            Wt[f * 4 + 1][k] = v.y;
            Wt[f * 4 + 2][k] = v.z;
            Wt[f * 4 + 3][k] = v.w;
        }
        __syncthreads();

#pragma unroll 4
        for (int s = 0; s < 32; ++s) {
            unsigned long long x2[4];
#pragma unroll
            for (int i = 0; i < 4; ++i)
                x2[i] = *(const unsigned long long*)&Xs[s][d0 + 2 * i];
#pragma unroll
            for (int j = 0; j < 8; ++j) {
                unsigned long long w2 = f2dup(Wt[s][tx + 32 * j]);
#pragma unroll
                for (int i = 0; i < 4; ++i) acc[i][j] = f2fma(x2[i], w2, acc[i][j]);
            }
        }
        __syncthreads();
    }

    float* dst = g_part + (size_t)(chunk * 32 + proj * 16 + b) * (DD * KPP);
#pragma unroll
    for (int i = 0; i < 4; ++i)
#pragma unroll
        for (int j = 0; j < 8; ++j) {
            float2 v = f2unpack(acc[i][j]);
            dst[(size_t)(d0 + 2 * i) * KPP + tx + 32 * j] = v.x;
            dst[(size_t)(d0 + 2 * i + 1) * KPP + tx + 32 * j] = v.y;
        }
}

// ======================================================================
// Kernel 2: reduce partials + bias. p=0 -> Kp[b][d][k]; p=1 -> Vp[b][k][d].
// ======================================================================
__global__ __launch_bounds__(256) void proj_reduce(const float* __restrict__ Eb,
                                                   const float* __restrict__ Fb) {
    int idx = blockIdx.x * 256 + threadIdx.x;  // 524288 total
    int p = idx >> 18;
    int rem = idx & 262143;
    int b = rem >> 14;
    int dk = rem & 16383;
    float s = 0.f;
#pragma unroll
    for (int c = 0; c < SCHUNKS; ++c)
        s += g_part[(size_t)(c * 32 + p * 16 + b) * 16384 + dk];
    if (p == 0) {
        int k = dk & 255;
        g_Kp[(size_t)b * 16384 + dk] = s + Eb[k];
    } else {
        int d = dk >> 8, k = dk & 255;
        g_Vp[(size_t)b * 16384 + k * 64 + d] = s + Fb[k];
    }
}

// ======================================================================
// Kernel 3: fused attention. grid (S/64, B), 256 threads, ~210 KB dyn smem.
//   smem: Kps[64][256], Vps[256][64], Qst[64][64] (transposed, scale folded),
//         Pst[256][66] (probs transposed, padded).
// ======================================================================
#define SM_K 0
#define SM_V 16384
#define SM_Q 32768
#define SM_P 36864
#define SM_FLOATS (36864 + 256 * 66) /* 53760 floats = 215040 B */

__global__ __launch_bounds__(256) void attn_kernel(const float* __restrict__ Q,
                                                   float* __restrict__ outp,
                                                   float* __restrict__ attnp) {
    extern __shared__ __align__(16) float sm[];
    float* Kps = sm + SM_K;  // [d][k]
    float* Vps = sm + SM_V;  // [k][d]
    float* Qst = sm + SM_Q;  // [d][row]
    float* Pst = sm + SM_P;  // [k][row] pad 66

    const int tid = threadIdx.x;
    const int b = blockIdx.y;
    const int srow0 = blockIdx.x * 64;

    // ---- Phase A: stage Kp, Vp, Q(T, scaled) ----
    const float* kp = g_Kp + (size_t)b * 16384;
    const float* vp = g_Vp + (size_t)b * 16384;
#pragma unroll
    for (int i = 0; i < 16; ++i) {
        int slot = tid + 256 * i;
        *(float4*)&Kps[slot * 4] = *(const float4*)&kp[slot * 4];
        *(float4*)&Vps[slot * 4] = *(const float4*)&vp[slot * 4];
    }
    const float* Qb = Q + ((size_t)b * SS + srow0) * DD;
#pragma unroll
    for (int i = 0; i < 4; ++i) {
        int slot = tid + 256 * i;  // 1024 float4 slots
        int r = slot >> 4, f = slot & 15;
        float4 v = *(const float4*)&Qb[(size_t)r * DD + f * 4];
        Qst[(f * 4 + 0) * 64 + r] = v.x * SCALE;
        Qst[(f * 4 + 1) * 64 + r] = v.y * SCALE;
        Qst[(f * 4 + 2) * 64 + r] = v.z * SCALE;
        Qst[(f * 4 + 3) * 64 + r] = v.w * SCALE;
    }
    __syncthreads();

    const int w = tid >> 5, lane = tid & 31;
    const int r0 = w * 8;  // this warp's 8 rows

    // ---- Phase B: scores = Q*scale @ Kp (row-paired f32x2) ----
    unsigned long long acc[4][8];
#pragma unroll
    for (int i = 0; i < 4; ++i)
#pragma unroll
        for (int j = 0; j < 8; ++j) acc[i][j] = 0ULL;

#pragma unroll 4
    for (int d = 0; d < 64; ++d) {
        unsigned long long q2[4];
#pragma unroll
        for (int i = 0; i < 4; ++i)
            q2[i] = *(const unsigned long long*)&Qst[d * 64 + r0 + 2 * i];
#pragma unroll
        for (int j = 0; j < 8; ++j) {
            unsigned long long kd = f2dup(Kps[d * 256 + lane + 32 * j]);
#pragma unroll
            for (int i = 0; i < 4; ++i) acc[i][j] = f2fma(q2[i], kd, acc[i][j]);
        }
    }

    // ---- softmax over k (k split across lanes: k = lane + 32j) ----
    float sc[8][8];
#pragma unroll
    for (int i = 0; i < 4; ++i)
#pragma unroll
        for (int j = 0; j < 8; ++j) {
            float2 v = f2unpack(acc[i][j]);
            sc[2 * i][j] = v.x;
            sc[2 * i + 1][j] = v.y;
        }

    float* attnbase = attnp + ((size_t)b * SS + srow0 + r0) * KPP + lane;
#pragma unroll
    for (int r = 0; r < 8; ++r) {
        float m = sc[r][0];
#pragma unroll
        for (int j = 1; j < 8; ++j) m = fmaxf(m, sc[r][j]);
#pragma unroll
        for (int off = 16; off > 0; off >>= 1)
            m = fmaxf(m, __shfl_xor_sync(0xffffffffu, m, off));
        float ssum = 0.f;
#pragma unroll
        for (int j = 0; j < 8; ++j) {
            float e = __expf(sc[r][j] - m);
            sc[r][j] = e;
            ssum += e;
        }
#pragma unroll
        for (int off = 16; off > 0; off >>= 1)
            ssum += __shfl_xor_sync(0xffffffffu, ssum, off);
        float inv = 1.0f / ssum;
#pragma unroll
        for (int j = 0; j < 8; ++j) {
            float pv = sc[r][j] * inv;
            Pst[(lane + 32 * j) * 66 + r0 + r] = pv;      // transposed probs
            attnbase[(size_t)r * KPP + 32 * j] = pv;      // coalesced global attn
        }
    }
    __syncthreads();

    // ---- Phase C: out = P @ Vp. lane tile: 2 rows x 8 d ----
    const int rg = lane >> 3;   // 0..3 -> row pair
    const int dg = lane & 7;    // 0..7 -> 8 d
    const int rl = r0 + 2 * rg;

    unsigned long long oacc[2][4];
#pragma unroll
    for (int r = 0; r < 2; ++r)
#pragma unroll
        for (int mI = 0; mI < 4; ++mI) oacc[r][mI] = 0ULL;

#pragma unroll 2
    for (int k = 0; k < 256; ++k) {
        float2 p = f2unpack(*(const unsigned long long*)&Pst[k * 66 + rl]);
        unsigned long long pd0 = f2dup(p.x);
        unsigned long long pd1 = f2dup(p.y);
        float4 vA = *(const float4*)&Vps[k * 64 + dg * 8];
        float4 vB = *(const float4*)&Vps[k * 64 + dg * 8 + 4];
        unsigned long long v0 = f2pack(vA.x, vA.y);
        unsigned long long v1 = f2pack(vA.z, vA.w);
        unsigned long long v2 = f2pack(vB.x, vB.y);
        unsigned long long v3 = f2pack(vB.z, vB.w);
        oacc[0][0] = f2fma(pd0, v0, oacc[0][0]);
        oacc[0][1] = f2fma(pd0, v1, oacc[0][1]);
        oacc[0][2] = f2fma(pd0, v2, oacc[0][2]);
        oacc[0][3] = f2fma(pd0, v3, oacc[0][3]);
        oacc[1][0] = f2fma(pd1, v0, oacc[1][0]);
        oacc[1][1] = f2fma(pd1, v1, oacc[1][1]);
        oacc[1][2] = f2fma(pd1, v2, oacc[1][2]);
        oacc[1][3] = f2fma(pd1, v3, oacc[1][3]);
    }

#pragma unroll
    for (int r = 0; r < 2; ++r) {
        float2 a = f2unpack(oacc[r][0]);
        float2 c = f2unpack(oacc[r][1]);
        float2 e = f2unpack(oacc[r][2]);
        float2 g = f2unpack(oacc[r][3]);
        float* o = outp + ((size_t)b * SS + srow0 + rl + r) * DD + dg * 8;
        *(float4*)&o[0] = make_float4(a.x, a.y, c.x, c.y);
        *(float4*)&o[4] = make_float4(e.x, e.y, g.x, g.y);
    }
}

// ======================================================================
extern "C" void kernel_launch(void* const* d_in, const int* in_sizes, int n_in,
                              void* d_out, int out_size) {
    const float* Q  = (const float*)d_in[0];
    const float* K  = (const float*)d_in[1];
    const float* V  = (const float*)d_in[2];
    const float* Ew = (const float*)d_in[3];
    const float* Eb = (const float*)d_in[4];
    const float* Fw = (const float*)d_in[5];
    const float* Fb = (const float*)d_in[6];

    float* outp  = (float*)d_out;                       // [B,S,D] first
    float* attnp = outp + (size_t)BB * SS * DD;         // then [B,S,KP]

    const size_t smem = (size_t)SM_FLOATS * sizeof(float);  // 215040 B
    cudaFuncSetAttribute(attn_kernel, cudaFuncAttributeMaxDynamicSharedMemorySize,
                         (int)smem);

    proj_partial<<<dim3(SCHUNKS, BB, 2), 256>>>(K, V, Ew, Fw);
    proj_reduce<<<2048, 256>>>(Eb, Fb);
    attn_kernel<<<dim3(SS / 64, BB), 256, smem>>>(Q, outp, attnp);
}

// round 3
// speedup vs baseline: 1.1087x; 1.1087x over previous
#include <cuda_runtime.h>
#include <cuda_bf16.h>
#include <cstdint>

#define BB 16
#define SS 4096
#define DD 64
#define KPP 256
#define SCALE 0.125f

// ---------------- device scratch ----------------
__device__ float g_part8[8 * 2 * 16 * 256 * 64]; // [chunk][proj][b][m256][n64] 16MB
__device__ float g_Kp[BB * DD * KPP];            // [b][d][k]
__device__ float g_Vp[BB * KPP * DD];            // [b][k][d]

// ---------------- f32x2 helpers (Blackwell FFMA2) ----------------
__device__ __forceinline__ unsigned long long f2fma(unsigned long long a,
                                                    unsigned long long b,
                                                    unsigned long long c) {
    unsigned long long d_;
    asm("fma.rn.f32x2 %0, %1, %2, %3;" : "=l"(d_) : "l"(a), "l"(b), "l"(c));
    return d_;
}
__device__ __forceinline__ unsigned long long f2add(unsigned long long a,
                                                    unsigned long long b) {
    unsigned long long d_;
    asm("add.rn.f32x2 %0, %1, %2;" : "=l"(d_) : "l"(a), "l"(b));
    return d_;
}
__device__ __forceinline__ unsigned long long f2dup(float x) {
    unsigned long long d_;
    asm("mov.b64 %0, {%1, %1};" : "=l"(d_) : "f"(x));
    return d_;
}
__device__ __forceinline__ float2 f2unpack(unsigned long long v) {
    float lo, hi;
    asm("mov.b64 {%0, %1}, %2;" : "=f"(lo), "=f"(hi) : "l"(v));
    return make_float2(lo, hi);
}

// ---------------- mma.sync helpers ----------------
__device__ __forceinline__ uint32_t smem_u32(const void* p) {
    uint32_t a;
    asm("{ .reg .u64 t; cvta.to.shared.u64 t, %1; cvt.u32.u64 %0, t; }" : "=r"(a) : "l"(p));
    return a;
}
__device__ __forceinline__ void ldm_x4(uint32_t* r, uint32_t addr) {
    asm volatile("ldmatrix.sync.aligned.m8n8.x4.shared.b16 {%0,%1,%2,%3}, [%4];"
                 : "=r"(r[0]), "=r"(r[1]), "=r"(r[2]), "=r"(r[3]) : "r"(addr));
}
__device__ __forceinline__ void mma_bf16(float* c, const uint32_t* a, const uint32_t* b) {
    asm volatile(
        "mma.sync.aligned.m16n8k16.row.col.f32.bf16.bf16.f32 "
        "{%0,%1,%2,%3}, {%4,%5,%6,%7}, {%8,%9}, {%0,%1,%2,%3};"
        : "+f"(c[0]), "+f"(c[1]), "+f"(c[2]), "+f"(c[3])
        : "r"(a[0]), "r"(a[1]), "r"(a[2]), "r"(a[3]), "r"(b[0]), "r"(b[1]));
}
__device__ __forceinline__ void sp2(float x, __nv_bfloat16& h, __nv_bfloat16& l) {
    h = __float2bfloat16(x);
    l = __float2bfloat16(x - __bfloat162float(h));
}
__device__ __forceinline__ uint32_t bpk(__nv_bfloat16 a, __nv_bfloat16 b) {
    __nv_bfloat162 t = __halves2bfloat162(a, b);
    return *reinterpret_cast<uint32_t*>(&t);
}

// ======================================================================
// Kernel 1: projections via mma.sync bf16-split.
//   C[m=KP 256][n=d 64] = sum_s W[m][s] * X[s][n], K-slice of 512 per CTA.
// grid (8 chunk, 2 proj, 16 b), 256 thr, 40KB static smem, 2 CTA/SM.
// smem layout: atom-packed 8x8 bf16 tiles (128B each, contiguous).
//   A atoms: [(m/8)*4 + k8g]*64 + (m%8)*8 + (k%8)   (m: 256, k: 32/stage)
//   B atoms: [(d/8)*4 + s8g]*64 + (d%8)*8 + (s%8)   (Bt[d][s])
// ======================================================================
__global__ __launch_bounds__(256, 2) void proj_mma(const float* __restrict__ Kin,
                                                   const float* __restrict__ Vin,
                                                   const float* __restrict__ Ew,
                                                   const float* __restrict__ Fw) {
    __shared__ __align__(1024) __nv_bfloat16 Ahi[256 * 32];
    __shared__ __align__(1024) __nv_bfloat16 Alo[256 * 32];
    __shared__ __align__(1024) __nv_bfloat16 Bhi[64 * 32];
    __shared__ __align__(1024) __nv_bfloat16 Blo[64 * 32];

    const int tid = threadIdx.x, lane = tid & 31, w = tid >> 5;
    const int chunk = blockIdx.x, proj = blockIdx.y, b = blockIdx.z;
    const int wm = w & 3, wn = w >> 2;

    const float* W = (proj ? Fw : Ew) + chunk * 512;                      // row stride SS
    const float* X = (proj ? Vin : Kin) + ((size_t)b * SS + chunk * 512) * DD;

    const uint32_t aHi = smem_u32(Ahi), aLo = smem_u32(Alo);
    const uint32_t bHi = smem_u32(Bhi), bLo = smem_u32(Blo);

    // per-lane ldmatrix byte offsets (without mt/nt2/kk2 terms)
    // A: ((wm*8 + mt*2 + b3)*4 + kk2*2 + b4)*128 + (lane&7)*16
    const int b3 = (lane >> 3) & 1, b4 = lane >> 4, r7 = (lane & 7) * 16;
    // B: ((wn*4 + nt2*2 + b4)*4 + kk2*2 + b3)*128 + r7

    float acc[4][4][4];
#pragma unroll
    for (int i = 0; i < 4; ++i)
#pragma unroll
        for (int j = 0; j < 4; ++j)
#pragma unroll
            for (int e = 0; e < 4; ++e) acc[i][j][e] = 0.f;

    const float* wrow = W + (size_t)tid * SS;

    for (int st = 0; st < 16; ++st) {
        // ---- stage A: row tid, 32 k-floats -> hi/lo bf16 atoms ----
        {
            const float* src = wrow + st * 32;
            float4 f[8];
#pragma unroll
            for (int j = 0; j < 8; ++j) f[j] = *(const float4*)(src + j * 4);
#pragma unroll
            for (int kg = 0; kg < 4; ++kg) {
                float v[8] = {f[2 * kg].x, f[2 * kg].y, f[2 * kg].z, f[2 * kg].w,
                              f[2 * kg + 1].x, f[2 * kg + 1].y, f[2 * kg + 1].z, f[2 * kg + 1].w};
                __nv_bfloat16 h[8], l[8];
#pragma unroll
                for (int e = 0; e < 8; ++e) sp2(v[e], h[e], l[e]);
                int off = ((tid >> 3) * 4 + kg) * 64 + (tid & 7) * 8;
                uint4 uh = make_uint4(bpk(h[0], h[1]), bpk(h[2], h[3]), bpk(h[4], h[5]), bpk(h[6], h[7]));
                uint4 ul = make_uint4(bpk(l[0], l[1]), bpk(l[2], l[3]), bpk(l[4], l[5]), bpk(l[6], l[7]));
                *(uint4*)&Ahi[off] = uh;
                *(uint4*)&Alo[off] = ul;
            }
        }
        // ---- stage B: X[32 s][64 d] -> Bt atoms ----
#pragma unroll
        for (int i = 0; i < 2; ++i) {
            int slot = tid + 256 * i;
            int s = slot >> 4, dq = slot & 15;
            float4 v = *(const float4*)&X[((size_t)st * 32 + s) * DD + dq * 4];
            float vv[4] = {v.x, v.y, v.z, v.w};
#pragma unroll
            for (int e = 0; e < 4; ++e) {
                int d = dq * 4 + e;
                __nv_bfloat16 h, l;
                sp2(vv[e], h, l);
                int off = ((d >> 3) * 4 + (s >> 3)) * 64 + (d & 7) * 8 + (s & 7);
                Bhi[off] = h;
                Blo[off] = l;
            }
        }
        __syncthreads();

        // ---- compute: 2 k16 groups ----
#pragma unroll
        for (int kk2 = 0; kk2 < 2; ++kk2) {
            uint32_t ah[4][4], al[4][4], bh[2][4], bl[2][4];
#pragma unroll
            for (int mt = 0; mt < 4; ++mt) {
                uint32_t o = (uint32_t)(((wm * 8 + mt * 2 + b3) * 4 + kk2 * 2 + b4) * 128 + r7);
                ldm_x4(ah[mt], aHi + o);
                ldm_x4(al[mt], aLo + o);
            }
#pragma unroll
            for (int nt2 = 0; nt2 < 2; ++nt2) {
                uint32_t o = (uint32_t)(((wn * 4 + nt2 * 2 + b4) * 4 + kk2 * 2 + b3) * 128 + r7);
                ldm_x4(bh[nt2], bHi + o);
                ldm_x4(bl[nt2], bLo + o);
            }
#pragma unroll
            for (int mt = 0; mt < 4; ++mt)
#pragma unroll
                for (int nt2 = 0; nt2 < 2; ++nt2)
#pragma unroll
                    for (int hf = 0; hf < 2; ++hf) {
                        int nt = nt2 * 2 + hf;
                        mma_bf16(acc[mt][nt], ah[mt], &bh[nt2][hf * 2]);
                        mma_bf16(acc[mt][nt], ah[mt], &bl[nt2][hf * 2]);
                        mma_bf16(acc[mt][nt], al[mt], &bh[nt2][hf * 2]);
                    }
        }
        __syncthreads();
    }

    // ---- store C fragments to partials ----
    float* dst = g_part8 + ((size_t)(chunk * 2 + proj) * 16 + b) * 16384;
    const int row = lane >> 2, q2 = (lane & 3) * 2;
#pragma unroll
    for (int mt = 0; mt < 4; ++mt)
#pragma unroll
        for (int nt = 0; nt < 4; ++nt) {
            int m = wm * 64 + mt * 16 + row;
            int n = wn * 32 + nt * 8 + q2;
            *(float2*)&dst[(size_t)m * 64 + n] = make_float2(acc[mt][nt][0], acc[mt][nt][1]);
            *(float2*)&dst[(size_t)(m + 8) * 64 + n] = make_float2(acc[mt][nt][2], acc[mt][nt][3]);
        }
}

// ======================================================================
// Kernel 2: reduce 8 chunk-partials + bias -> g_Kp (transposed), g_Vp.
// ======================================================================
__global__ __launch_bounds__(256) void proj_reduce8(const float* __restrict__ Eb,
                                                    const float* __restrict__ Fb) {
    int idx = blockIdx.x * 256 + threadIdx.x; // 131072 threads, float4 each
    int nq = idx & 15, m = (idx >> 4) & 255, b = (idx >> 12) & 15, p = idx >> 16;
    float4 s = make_float4(0.f, 0.f, 0.f, 0.f);
#pragma unroll
    for (int c = 0; c < 8; ++c) {
        const float4 v = *(const float4*)&g_part8[((size_t)(c * 2 + p) * 16 + b) * 16384 +
                                                  (size_t)m * 64 + nq * 4];
        s.x += v.x; s.y += v.y; s.z += v.z; s.w += v.w;
    }
    if (p == 0) {
        float bias = Eb[m];
        float* kp = g_Kp + (size_t)b * 16384;
        kp[(nq * 4 + 0) * 256 + m] = s.x + bias;
        kp[(nq * 4 + 1) * 256 + m] = s.y + bias;
        kp[(nq * 4 + 2) * 256 + m] = s.z + bias;
        kp[(nq * 4 + 3) * 256 + m] = s.w + bias;
    } else {
        float bias = Fb[m];
        float4 o = make_float4(s.x + bias, s.y + bias, s.z + bias, s.w + bias);
        *(float4*)&g_Vp[(size_t)b * 16384 + (size_t)m * 64 + nq * 4] = o;
    }
}

extern __shared__ __align__(1024) char dsm[];

// ======================================================================
// Kernel 3: scores + softmax + attn write. grid (S/64, B), 256 thr, 80KB smem.
// ======================================================================
#define AS_Q 16384
#define AS_SMEM ((16384 + 4096) * 4)

__global__ __launch_bounds__(256) void attn_score(const float* __restrict__ Q,
                                                  float* __restrict__ attnp) {
    float* Kps = (float*)dsm;        // [d][k] 64x256
    float* Qst = (float*)dsm + AS_Q; // [d][row] 64x64
    const int tid = threadIdx.x;
    const int b = blockIdx.y;
    const int srow0 = blockIdx.x * 64;

    const float* kp = g_Kp + (size_t)b * 16384;
#pragma unroll
    for (int i = 0; i < 16; ++i) {
        int slot = tid + 256 * i;
        *(float4*)&Kps[slot * 4] = *(const float4*)&kp[slot * 4];
    }
    const float* Qb = Q + ((size_t)b * SS + srow0) * DD;
#pragma unroll
    for (int i = 0; i < 4; ++i) {
        int slot = tid + 256 * i;
        int r = slot >> 4, f = slot & 15;
        float4 v = *(const float4*)&Qb[(size_t)r * DD + f * 4];
        Qst[(f * 4 + 0) * 64 + r] = v.x * SCALE;
        Qst[(f * 4 + 1) * 64 + r] = v.y * SCALE;
        Qst[(f * 4 + 2) * 64 + r] = v.z * SCALE;
        Qst[(f * 4 + 3) * 64 + r] = v.w * SCALE;
    }
    __syncthreads();

    const int w = tid >> 5, lane = tid & 31;
    const int r0 = w * 8;

    unsigned long long acc[4][8];
#pragma unroll
    for (int i = 0; i < 4; ++i)
#pragma unroll
        for (int j = 0; j < 8; ++j) acc[i][j] = 0ULL;

#pragma unroll 4
    for (int d = 0; d < 64; ++d) {
        unsigned long long q2[4];
#pragma unroll
        for (int i = 0; i < 4; ++i)
            q2[i] = *(const unsigned long long*)&Qst[d * 64 + r0 + 2 * i];
#pragma unroll
        for (int j = 0; j < 8; ++j) {
            unsigned long long kd = f2dup(Kps[d * 256 + lane + 32 * j]);
#pragma unroll
            for (int i = 0; i < 4; ++i) acc[i][j] = f2fma(q2[i], kd, acc[i][j]);
        }
    }

    float sc[8][8];
#pragma unroll
    for (int i = 0; i < 4; ++i)
#pragma unroll
        for (int j = 0; j < 8; ++j) {
            float2 v = f2unpack(acc[i][j]);
            sc[2 * i][j] = v.x;
            sc[2 * i + 1][j] = v.y;
        }

    float* attnbase = attnp + ((size_t)b * SS + srow0 + r0) * KPP + lane;
#pragma unroll
    for (int r = 0; r < 8; ++r) {
        float m = sc[r][0];
#pragma unroll
        for (int j = 1; j < 8; ++j) m = fmaxf(m, sc[r][j]);
#pragma unroll
        for (int off = 16; off > 0; off >>= 1)
            m = fmaxf(m, __shfl_xor_sync(0xffffffffu, m, off));
        float ssum = 0.f;
#pragma unroll
        for (int j = 0; j < 8; ++j) {
            float e = __expf(sc[r][j] - m);
            sc[r][j] = e;
            ssum += e;
        }
#pragma unroll
        for (int off = 16; off > 0; off >>= 1)
            ssum += __shfl_xor_sync(0xffffffffu, ssum, off);
        float inv = 1.0f / ssum;
#pragma unroll
        for (int j = 0; j < 8; ++j)
            attnbase[(size_t)r * KPP + 32 * j] = sc[r][j] * inv;
    }
}

// ======================================================================
// Kernel 4: out = attn @ Vp. grid (S/32, B), 256 thr, 105KB smem.
// ======================================================================
#define AO_V 33792
#define AO_RED (AO_V + 65536)
#define AO_SMEM (AO_RED + 8192)

__global__ __launch_bounds__(256) void attn_out(const float* __restrict__ attnp,
                                                float* __restrict__ outp) {
    float* Pst = (float*)dsm;             // [k][33]
    float* Vps = (float*)(dsm + AO_V);    // [k][64]
    float* Ored = (float*)(dsm + AO_RED); // [row32][64]
    const int tid = threadIdx.x, w = tid >> 5, lane = tid & 31;
    const int b = blockIdx.y, s0 = blockIdx.x * 32;

    const float* vp = g_Vp + (size_t)b * 16384;
#pragma unroll
    for (int i = 0; i < 16; ++i) {
        int slot = tid + 256 * i;
        *(float4*)&Vps[slot * 4] = *(const float4*)&vp[slot * 4];
    }
    const float* ap = attnp + ((size_t)b * SS + s0) * KPP;
#pragma unroll
    for (int r = 0; r < 4; ++r) {
        int row = w * 4 + r;
#pragma unroll
        for (int c = 0; c < 8; ++c) {
            int k = c * 32 + lane;
            Pst[k * 33 + row] = ap[(size_t)row * KPP + k];
        }
    }
    __syncthreads();

    const int khalf = w & 1;
    const int rg8 = (w >> 1) * 8;
    const int rp = lane >> 3, dg = lane & 7;
    const int r0 = rg8 + 2 * rp;

    unsigned long long acc[2][4];
#pragma unroll
    for (int r = 0; r < 2; ++r)
#pragma unroll
        for (int i = 0; i < 4; ++i) acc[r][i] = 0ULL;

    const int kb = khalf * 128;
#pragma unroll 4
    for (int kk = 0; kk < 128; ++kk) {
        int k = kb + kk;
        unsigned long long pd0 = f2dup(Pst[k * 33 + r0]);
        unsigned long long pd1 = f2dup(Pst[k * 33 + r0 + 1]);
        const unsigned long long* vrow = (const unsigned long long*)&Vps[k * 64 + dg * 8];
#pragma unroll
        for (int i = 0; i < 4; ++i) {
            unsigned long long v = vrow[i];
            acc[0][i] = f2fma(pd0, v, acc[0][i]);
            acc[1][i] = f2fma(pd1, v, acc[1][i]);
        }
    }
    if (khalf) {
#pragma unroll
        for (int r = 0; r < 2; ++r)
#pragma unroll
            for (int i = 0; i < 4; ++i)
                *(unsigned long long*)&Ored[(r0 + r) * 64 + dg * 8 + 2 * i] = acc[r][i];
    }
    __syncthreads();
    if (!khalf) {
#pragma unroll
        for (int r = 0; r < 2; ++r) {
#pragma unroll
            for (int i = 0; i < 4; ++i)
                acc[r][i] = f2add(acc[r][i],
                                  *(const unsigned long long*)&Ored[(r0 + r) * 64 + dg * 8 + 2 * i]);
            float2 a = f2unpack(acc[r][0]), c2 = f2unpack(acc[r][1]);
            float2 e = f2unpack(acc[r][2]), g = f2unpack(acc[r][3]);
            float* o = outp + ((size_t)b * SS + s0 + r0 + r) * DD + dg * 8;
            *(float4*)&o[0] = make_float4(a.x, a.y, c2.x, c2.y);
            *(float4*)&o[4] = make_float4(e.x, e.y, g.x, g.y);
        }
    }
}

// ======================================================================
extern "C" void kernel_launch(void* const* d_in, const int* in_sizes, int n_in,
                              void* d_out, int out_size) {
    const float* Q  = (const float*)d_in[0];
    const float* K  = (const float*)d_in[1];
    const float* V  = (const float*)d_in[2];
    const float* Ew = (const float*)d_in[3];
    const float* Eb = (const float*)d_in[4];
    const float* Fw = (const float*)d_in[5];
    const float* Fb = (const float*)d_in[6];

    float* outp  = (float*)d_out;
    float* attnp = outp + (size_t)BB * SS * DD;

    cudaFuncSetAttribute(attn_score, cudaFuncAttributeMaxDynamicSharedMemorySize, AS_SMEM);
    cudaFuncSetAttribute(attn_out, cudaFuncAttributeMaxDynamicSharedMemorySize, AO_SMEM);

    proj_mma<<<dim3(8, 2, BB), 256>>>(K, V, Ew, Fw);
    proj_reduce8<<<512, 256>>>(Eb, Fb);
    attn_score<<<dim3(SS / 64, BB), 256, AS_SMEM>>>(Q, attnp);
    attn_out<<<dim3(SS / 32, BB), 256, AO_SMEM>>>(attnp, outp);
}

// round 4
// speedup vs baseline: 2.0971x; 1.8916x over previous
#include <cuda_runtime.h>
#include <cuda_bf16.h>
#include <cstdint>

#define BB 16
#define SS 4096
#define DD 64
#define KPP 256
#define SCALE 0.125f

// ---------------- device scratch ----------------
__device__ float g_part8[8 * 2 * 16 * 256 * 64]; // [chunk][proj][b][m256][n64] 16MB
// Kp as B-operand atoms for scores: n=kp(256), k=d(64); atom=(n8*8+k8), entry=(n%8)*8+(k%8)
__device__ __nv_bfloat16 g_KpBhi[BB * 256 * 64];
__device__ __nv_bfloat16 g_KpBlo[BB * 256 * 64];
// Vp as B-operand atoms for out: n=d(64), k=kp(256); atom=(n8*32+k8), entry=(n%8)*8+(k%8)
__device__ __nv_bfloat16 g_VpBhi[BB * 256 * 64];
__device__ __nv_bfloat16 g_VpBlo[BB * 256 * 64];

// ---------------- mma.sync helpers (validated R3) ----------------
__device__ __forceinline__ uint32_t smem_u32(const void* p) {
    uint32_t a;
    asm("{ .reg .u64 t; cvta.to.shared.u64 t, %1; cvt.u32.u64 %0, t; }" : "=r"(a) : "l"(p));
    return a;
}
__device__ __forceinline__ void ldm_x4(uint32_t* r, uint32_t addr) {
    asm volatile("ldmatrix.sync.aligned.m8n8.x4.shared.b16 {%0,%1,%2,%3}, [%4];"
                 : "=r"(r[0]), "=r"(r[1]), "=r"(r[2]), "=r"(r[3]) : "r"(addr));
}
__device__ __forceinline__ void mma_bf16(float* c, const uint32_t* a, const uint32_t* b) {
    asm volatile(
        "mma.sync.aligned.m16n8k16.row.col.f32.bf16.bf16.f32 "
        "{%0,%1,%2,%3}, {%4,%5,%6,%7}, {%8,%9}, {%0,%1,%2,%3};"
        : "+f"(c[0]), "+f"(c[1]), "+f"(c[2]), "+f"(c[3])
        : "r"(a[0]), "r"(a[1]), "r"(a[2]), "r"(a[3]), "r"(b[0]), "r"(b[1]));
}
__device__ __forceinline__ void sp2(float x, __nv_bfloat16& h, __nv_bfloat16& l) {
    h = __float2bfloat16(x);
    l = __float2bfloat16(x - __bfloat162float(h));
}
__device__ __forceinline__ uint32_t bpk(__nv_bfloat16 a, __nv_bfloat16 b) {
    __nv_bfloat162 t = __halves2bfloat162(a, b);
    return *reinterpret_cast<uint32_t*>(&t);
}
__device__ __forceinline__ void splitpack(float v0, float v1, uint32_t& h, uint32_t& l) {
    __nv_bfloat16 h0, l0, h1, l1;
    sp2(v0, h0, l0);
    sp2(v1, h1, l1);
    h = bpk(h0, h1);
    l = bpk(l0, l1);
}

// ======================================================================
// Kernel 1: projections via mma.sync bf16-split (unchanged from R3).
// ======================================================================
__global__ __launch_bounds__(256, 2) void proj_mma(const float* __restrict__ Kin,
                                                   const float* __restrict__ Vin,
                                                   const float* __restrict__ Ew,
                                                   const float* __restrict__ Fw) {
    __shared__ __align__(1024) __nv_bfloat16 Ahi[256 * 32];
    __shared__ __align__(1024) __nv_bfloat16 Alo[256 * 32];
    __shared__ __align__(1024) __nv_bfloat16 Bhi[64 * 32];
    __shared__ __align__(1024) __nv_bfloat16 Blo[64 * 32];

    const int tid = threadIdx.x, lane = tid & 31, w = tid >> 5;
    const int chunk = blockIdx.x, proj = blockIdx.y, b = blockIdx.z;
    const int wm = w & 3, wn = w >> 2;

    const float* W = (proj ? Fw : Ew) + chunk * 512;
    const float* X = (proj ? Vin : Kin) + ((size_t)b * SS + chunk * 512) * DD;

    const uint32_t aHi = smem_u32(Ahi), aLo = smem_u32(Alo);
    const uint32_t bHi = smem_u32(Bhi), bLo = smem_u32(Blo);

    const int b3 = (lane >> 3) & 1, b4 = lane >> 4, r7 = (lane & 7) * 16;

    float acc[4][4][4];
#pragma unroll
    for (int i = 0; i < 4; ++i)
#pragma unroll
        for (int j = 0; j < 4; ++j)
#pragma unroll
            for (int e = 0; e < 4; ++e) acc[i][j][e] = 0.f;

    const float* wrow = W + (size_t)tid * SS;

    for (int st = 0; st < 16; ++st) {
        {
            const float* src = wrow + st * 32;
            float4 f[8];
#pragma unroll
            for (int j = 0; j < 8; ++j) f[j] = *(const float4*)(src + j * 4);
#pragma unroll
            for (int kg = 0; kg < 4; ++kg) {
                float v[8] = {f[2 * kg].x, f[2 * kg].y, f[2 * kg].z, f[2 * kg].w,
                              f[2 * kg + 1].x, f[2 * kg + 1].y, f[2 * kg + 1].z, f[2 * kg + 1].w};
                __nv_bfloat16 h[8], l[8];
#pragma unroll
                for (int e = 0; e < 8; ++e) sp2(v[e], h[e], l[e]);
                int off = ((tid >> 3) * 4 + kg) * 64 + (tid & 7) * 8;
                uint4 uh = make_uint4(bpk(h[0], h[1]), bpk(h[2], h[3]), bpk(h[4], h[5]), bpk(h[6], h[7]));
                uint4 ul = make_uint4(bpk(l[0], l[1]), bpk(l[2], l[3]), bpk(l[4], l[5]), bpk(l[6], l[7]));
                *(uint4*)&Ahi[off] = uh;
                *(uint4*)&Alo[off] = ul;
            }
        }
#pragma unroll
        for (int i = 0; i < 2; ++i) {
            int slot = tid + 256 * i;
            int s = slot >> 4, dq = slot & 15;
            float4 v = *(const float4*)&X[((size_t)st * 32 + s) * DD + dq * 4];
            float vv[4] = {v.x, v.y, v.z, v.w};
#pragma unroll
            for (int e = 0; e < 4; ++e) {
                int d = dq * 4 + e;
                __nv_bfloat16 h, l;
                sp2(vv[e], h, l);
                int off = ((d >> 3) * 4 + (s >> 3)) * 64 + (d & 7) * 8 + (s & 7);
                Bhi[off] = h;
                Blo[off] = l;
            }
        }
        __syncthreads();

#pragma unroll
        for (int kk2 = 0; kk2 < 2; ++kk2) {
            uint32_t ah[4][4], al[4][4], bh[2][4], bl[2][4];
#pragma unroll
            for (int mt = 0; mt < 4; ++mt) {
                uint32_t o = (uint32_t)(((wm * 8 + mt * 2 + b3) * 4 + kk2 * 2 + b4) * 128 + r7);
                ldm_x4(ah[mt], aHi + o);
                ldm_x4(al[mt], aLo + o);
            }
#pragma unroll
            for (int nt2 = 0; nt2 < 2; ++nt2) {
                uint32_t o = (uint32_t)(((wn * 4 + nt2 * 2 + b4) * 4 + kk2 * 2 + b3) * 128 + r7);
                ldm_x4(bh[nt2], bHi + o);
                ldm_x4(bl[nt2], bLo + o);
            }
#pragma unroll
            for (int mt = 0; mt < 4; ++mt)
#pragma unroll
                for (int nt2 = 0; nt2 < 2; ++nt2)
#pragma unroll
                    for (int hf = 0; hf < 2; ++hf) {
                        int nt = nt2 * 2 + hf;
                        mma_bf16(acc[mt][nt], ah[mt], &bh[nt2][hf * 2]);
                        mma_bf16(acc[mt][nt], ah[mt], &bl[nt2][hf * 2]);
                        mma_bf16(acc[mt][nt], al[mt], &bh[nt2][hf * 2]);
                    }
        }
        __syncthreads();
    }

    float* dst = g_part8 + ((size_t)(chunk * 2 + proj) * 16 + b) * 16384;
    const int row = lane >> 2, q2 = (lane & 3) * 2;
#pragma unroll
    for (int mt = 0; mt < 4; ++mt)
#pragma unroll
        for (int nt = 0; nt < 4; ++nt) {
            int m = wm * 64 + mt * 16 + row;
            int n = wn * 32 + nt * 8 + q2;
            *(float2*)&dst[(size_t)m * 64 + n] = make_float2(acc[mt][nt][0], acc[mt][nt][1]);
            *(float2*)&dst[(size_t)(m + 8) * 64 + n] = make_float2(acc[mt][nt][2], acc[mt][nt][3]);
        }
}

// ======================================================================
// Kernel 2: reduce partials + bias -> bf16 hi/lo ATOM arrays in global.
// grid (4 kp-blocks, 2 proj, 16 b), 256 thr. Tile [64 kp][64 d].
// ======================================================================
__global__ __launch_bounds__(256) void proj_reduce_atoms(const float* __restrict__ Eb,
                                                         const float* __restrict__ Fb) {
    __shared__ float tile[64][65];
    const int tid = threadIdx.x;
    const int kpblk = blockIdx.x, p = blockIdx.y, b = blockIdx.z;

    float4 acc[4] = {make_float4(0, 0, 0, 0), make_float4(0, 0, 0, 0),
                     make_float4(0, 0, 0, 0), make_float4(0, 0, 0, 0)};
#pragma unroll
    for (int c = 0; c < 8; ++c) {
        const float* src = g_part8 + ((size_t)(c * 2 + p) * 16 + b) * 16384 + (size_t)kpblk * 4096;
#pragma unroll
        for (int i = 0; i < 4; ++i) {
            int slot = tid + 256 * i;
            float4 v = *(const float4*)&src[(slot >> 4) * 64 + (slot & 15) * 4];
            acc[i].x += v.x; acc[i].y += v.y; acc[i].z += v.z; acc[i].w += v.w;
        }
    }
    const float* bias = p ? Fb : Eb;
#pragma unroll
    for (int i = 0; i < 4; ++i) {
        int slot = tid + 256 * i;
        int r = slot >> 4, c4 = slot & 15;
        float bv = bias[kpblk * 64 + r];
        tile[r][c4 * 4 + 0] = acc[i].x + bv;
        tile[r][c4 * 4 + 1] = acc[i].y + bv;
        tile[r][c4 * 4 + 2] = acc[i].z + bv;
        tile[r][c4 * 4 + 3] = acc[i].w + bv;
    }
    __syncthreads();

    const int a = tid >> 2, rr0 = (tid & 3) * 2;
    const int g1 = a >> 3, g2 = a & 7;
    if (p == 0) {
        // Kp atoms: n8 = kp group (kpblk*8+g1), k8 = d group (g2); entry (kp%8)*8+(d%8)
        size_t gbase = (size_t)b * 16384 + (size_t)(((kpblk * 8 + g1) * 8 + g2)) * 64;
#pragma unroll
        for (int rr = rr0; rr < rr0 + 2; ++rr) {
            __nv_bfloat16 h[8], l[8];
#pragma unroll
            for (int j = 0; j < 8; ++j) sp2(tile[g1 * 8 + rr][g2 * 8 + j], h[j], l[j]);
            *(uint4*)&g_KpBhi[gbase + rr * 8] =
                make_uint4(bpk(h[0], h[1]), bpk(h[2], h[3]), bpk(h[4], h[5]), bpk(h[6], h[7]));
            *(uint4*)&g_KpBlo[gbase + rr * 8] =
                make_uint4(bpk(l[0], l[1]), bpk(l[2], l[3]), bpk(l[4], l[5]), bpk(l[6], l[7]));
        }
    } else {
        // Vp atoms: n8 = d group (g1), k8 = kp group (kpblk*8+g2); entry (d%8)*8+(kp%8)
        size_t gbase = (size_t)b * 16384 + (size_t)((g1 * 32 + kpblk * 8 + g2)) * 64;
#pragma unroll
        for (int rr = rr0; rr < rr0 + 2; ++rr) {
            __nv_bfloat16 h[8], l[8];
#pragma unroll
            for (int j = 0; j < 8; ++j) sp2(tile[g2 * 8 + j][g1 * 8 + rr], h[j], l[j]);
            *(uint4*)&g_VpBhi[gbase + rr * 8] =
                make_uint4(bpk(h[0], h[1]), bpk(h[2], h[3]), bpk(h[4], h[5]), bpk(h[6], h[7]));
            *(uint4*)&g_VpBlo[gbase + rr * 8] =
                make_uint4(bpk(l[0], l[1]), bpk(l[2], l[3]), bpk(l[4], l[5]), bpk(l[6], l[7]));
        }
    }
}

// ======================================================================
// Kernel 3: fused attention, fully tensor-core.
// CTA = 64 Q rows. grid (64, 16), 256 thr, 165 KB smem, 1 CTA/SM.
// warps: wm = w>>1 (m16 tile of 64 rows), wnh = w&1 (kp half of 128).
// ======================================================================
#define AT_QHI 0
#define AT_QLO 8192
#define AT_KHI 16384
#define AT_KLO 49152
#define AT_VHI 81920
#define AT_VLO 114688
#define AT_ORED 147456 /* float[64][66] */
#define AT_MAX 164352  /* float[128] */
#define AT_SUM 164864  /* float[128] */
#define AT_SMEM 165376

extern __shared__ __align__(1024) char dsm[];

__global__ __launch_bounds__(256, 1) void attn_fused(const float* __restrict__ Q,
                                                     float* __restrict__ attnp,
                                                     float* __restrict__ outp) {
    uint32_t smb = smem_u32(dsm);
    const int tid = threadIdx.x, lane = tid & 31, w = tid >> 5;
    const int b = blockIdx.y, s0 = blockIdx.x * 64;

    // ---- stage Kp/Vp atom arrays (pure copies) ----
    {
        const uint4* kh = (const uint4*)(g_KpBhi + (size_t)b * 16384);
        const uint4* kl = (const uint4*)(g_KpBlo + (size_t)b * 16384);
        const uint4* vh = (const uint4*)(g_VpBhi + (size_t)b * 16384);
        const uint4* vl = (const uint4*)(g_VpBlo + (size_t)b * 16384);
        uint4* dkh = (uint4*)(dsm + AT_KHI);
        uint4* dkl = (uint4*)(dsm + AT_KLO);
        uint4* dvh = (uint4*)(dsm + AT_VHI);
        uint4* dvl = (uint4*)(dsm + AT_VLO);
#pragma unroll
        for (int i = 0; i < 8; ++i) {
            int s = tid + 256 * i;
            dkh[s] = kh[s];
            dkl[s] = kl[s];
            dvh[s] = vh[s];
            dvl[s] = vl[s];
        }
    }
    // ---- build Q A-atoms (scale folded) ----
    {
        const float* Qb = Q + ((size_t)b * SS + s0) * DD;
        __nv_bfloat16* qh = (__nv_bfloat16*)(dsm + AT_QHI);
        __nv_bfloat16* ql = (__nv_bfloat16*)(dsm + AT_QLO);
#pragma unroll
        for (int i = 0; i < 4; ++i) {
            int slot = tid + 256 * i;
            int r = slot >> 4, d4 = slot & 15;
            float4 v = *(const float4*)&Qb[(size_t)r * DD + d4 * 4];
            __nv_bfloat16 h0, h1, h2, h3, l0, l1, l2, l3;
            sp2(v.x * SCALE, h0, l0);
            sp2(v.y * SCALE, h1, l1);
            sp2(v.z * SCALE, h2, l2);
            sp2(v.w * SCALE, h3, l3);
            int off = ((r >> 3) * 8 + (d4 >> 1)) * 64 + (r & 7) * 8 + (d4 & 1) * 4;
            *(uint2*)&qh[off] = make_uint2(bpk(h0, h1), bpk(h2, h3));
            *(uint2*)&ql[off] = make_uint2(bpk(l0, l1), bpk(l2, l3));
        }
    }
    __syncthreads();

    const int wm = w >> 1, wnh = w & 1;
    const int b3 = (lane >> 3) & 1, b4 = lane >> 4, r7 = (lane & 7) * 16;
    const uint32_t qhi = smb + AT_QHI, qlo = smb + AT_QLO;
    const uint32_t kphi = smb + AT_KHI, kplo = smb + AT_KLO;
    const uint32_t vphi = smb + AT_VHI, vplo = smb + AT_VLO;

    // ---- scores: C[m16][256-half] over k=d=64 ----
    float c[16][4];
#pragma unroll
    for (int i = 0; i < 16; ++i)
#pragma unroll
        for (int e = 0; e < 4; ++e) c[i][e] = 0.f;

#pragma unroll
    for (int kk = 0; kk < 4; ++kk) {
        uint32_t ah[4], al[4];
        uint32_t oA = (uint32_t)(((wm * 2 + b3) * 8 + kk * 2 + b4) * 128 + r7);
        ldm_x4(ah, qhi + oA);
        ldm_x4(al, qlo + oA);
#pragma unroll
        for (int nt2 = 0; nt2 < 8; ++nt2) {
            uint32_t bh[4], bl[4];
            uint32_t oB = (uint32_t)(((wnh * 16 + nt2 * 2 + b4) * 8 + kk * 2 + b3) * 128 + r7);
            ldm_x4(bh, kphi + oB);
            ldm_x4(bl, kplo + oB);
#pragma unroll
            for (int hf = 0; hf < 2; ++hf) {
                int nt = nt2 * 2 + hf;
                mma_bf16(c[nt], ah, &bh[hf * 2]);
                mma_bf16(c[nt], ah, &bl[hf * 2]);
                mma_bf16(c[nt], al, &bh[hf * 2]);
            }
        }
    }

    // ---- softmax over 256 (two warp-halves joined via smem) ----
    const int rl = wm * 16 + (lane >> 2);
    float* smax = (float*)(dsm + AT_MAX);
    float* ssum = (float*)(dsm + AT_SUM);

    float m0 = -1e30f, m1 = -1e30f;
#pragma unroll
    for (int nt = 0; nt < 16; ++nt) {
        m0 = fmaxf(m0, fmaxf(c[nt][0], c[nt][1]));
        m1 = fmaxf(m1, fmaxf(c[nt][2], c[nt][3]));
    }
#pragma unroll
    for (int off = 1; off <= 2; off <<= 1) {
        m0 = fmaxf(m0, __shfl_xor_sync(0xffffffffu, m0, off));
        m1 = fmaxf(m1, __shfl_xor_sync(0xffffffffu, m1, off));
    }
    if ((lane & 3) == 0) {
        smax[wnh * 64 + rl] = m0;
        smax[wnh * 64 + rl + 8] = m1;
    }
    __syncthreads();
    m0 = fmaxf(m0, smax[(wnh ^ 1) * 64 + rl]);
    m1 = fmaxf(m1, smax[(wnh ^ 1) * 64 + rl + 8]);

    float s0a = 0.f, s1a = 0.f;
#pragma unroll
    for (int nt = 0; nt < 16; ++nt) {
        c[nt][0] = __expf(c[nt][0] - m0);
        c[nt][1] = __expf(c[nt][1] - m0);
        c[nt][2] = __expf(c[nt][2] - m1);
        c[nt][3] = __expf(c[nt][3] - m1);
        s0a += c[nt][0] + c[nt][1];
        s1a += c[nt][2] + c[nt][3];
    }
#pragma unroll
    for (int off = 1; off <= 2; off <<= 1) {
        s0a += __shfl_xor_sync(0xffffffffu, s0a, off);
        s1a += __shfl_xor_sync(0xffffffffu, s1a, off);
    }
    if ((lane & 3) == 0) {
        ssum[wnh * 64 + rl] = s0a;
        ssum[wnh * 64 + rl + 8] = s1a;
    }
    __syncthreads();
    float inv0 = 1.f / (s0a + ssum[(wnh ^ 1) * 64 + rl]);
    float inv1 = 1.f / (s1a + ssum[(wnh ^ 1) * 64 + rl + 8]);

    // ---- scale probs + write attn ----
    float* abase = attnp + ((size_t)b * SS + s0 + rl) * KPP + wnh * 128 + (lane & 3) * 2;
#pragma unroll
    for (int nt = 0; nt < 16; ++nt) {
        c[nt][0] *= inv0;
        c[nt][1] *= inv0;
        c[nt][2] *= inv1;
        c[nt][3] *= inv1;
        *(float2*)&abase[nt * 8] = make_float2(c[nt][0], c[nt][1]);
        *(float2*)&abase[8 * KPP + nt * 8] = make_float2(c[nt][2], c[nt][3]);
    }

    // ---- out GEMM: P(frag, in regs) @ Vp, k-half per warp ----
    float oc[8][4];
#pragma unroll
    for (int i = 0; i < 8; ++i)
#pragma unroll
        for (int e = 0; e < 4; ++e) oc[i][e] = 0.f;

#pragma unroll
    for (int t2 = 0; t2 < 8; ++t2) {
        uint32_t pah[4], pal[4];
        splitpack(c[2 * t2][0], c[2 * t2][1], pah[0], pal[0]);
        splitpack(c[2 * t2][2], c[2 * t2][3], pah[1], pal[1]);
        splitpack(c[2 * t2 + 1][0], c[2 * t2 + 1][1], pah[2], pal[2]);
        splitpack(c[2 * t2 + 1][2], c[2 * t2 + 1][3], pah[3], pal[3]);
#pragma unroll
        for (int nt2 = 0; nt2 < 4; ++nt2) {
            uint32_t vh[4], vl[4];
            uint32_t oV = (uint32_t)(((nt2 * 2 + b4) * 32 + wnh * 16 + t2 * 2 + b3) * 128 + r7);
            ldm_x4(vh, vphi + oV);
            ldm_x4(vl, vplo + oV);
#pragma unroll
            for (int hf = 0; hf < 2; ++hf) {
                int nt = nt2 * 2 + hf;
                mma_bf16(oc[nt], pah, &vh[hf * 2]);
                mma_bf16(oc[nt], pah, &vl[hf * 2]);
                mma_bf16(oc[nt], pal, &vh[hf * 2]);
            }
        }
    }

    // ---- cross-half reduction + out write ----
    float* Ored = (float*)(dsm + AT_ORED); // [64][66]
    if (wnh == 1) {
#pragma unroll
        for (int nt = 0; nt < 8; ++nt) {
            int col = nt * 8 + (lane & 3) * 2;
            *(float2*)&Ored[rl * 66 + col] = make_float2(oc[nt][0], oc[nt][1]);
            *(float2*)&Ored[(rl + 8) * 66 + col] = make_float2(oc[nt][2], oc[nt][3]);
        }
    }
    __syncthreads();
    if (wnh == 0) {
        float* o0 = outp + ((size_t)b * SS + s0 + rl) * DD;
#pragma unroll
        for (int nt = 0; nt < 8; ++nt) {
            int col = nt * 8 + (lane & 3) * 2;
            float2 r0v = *(float2*)&Ored[rl * 66 + col];
            float2 r1v = *(float2*)&Ored[(rl + 8) * 66 + col];
            *(float2*)&o0[col] = make_float2(oc[nt][0] + r0v.x, oc[nt][1] + r0v.y);
            *(float2*)&o0[8 * DD + col] = make_float2(oc[nt][2] + r1v.x, oc[nt][3] + r1v.y);
        }
    }
}

// ======================================================================
extern "C" void kernel_launch(void* const* d_in, const int* in_sizes, int n_in,
                              void* d_out, int out_size) {
    const float* Q  = (const float*)d_in[0];
    const float* K  = (const float*)d_in[1];
    const float* V  = (const float*)d_in[2];
    const float* Ew = (const float*)d_in[3];
    const float* Eb = (const float*)d_in[4];
    const float* Fw = (const float*)d_in[5];
    const float* Fb = (const float*)d_in[6];

    float* outp  = (float*)d_out;
    float* attnp = outp + (size_t)BB * SS * DD;

    cudaFuncSetAttribute(attn_fused, cudaFuncAttributeMaxDynamicSharedMemorySize, AT_SMEM);

    proj_mma<<<dim3(8, 2, BB), 256>>>(K, V, Ew, Fw);
    proj_reduce_atoms<<<dim3(4, 2, BB), 256>>>(Eb, Fb);
    attn_fused<<<dim3(SS / 64, BB), 256, AT_SMEM>>>(Q, attnp, outp);
}

// round 5
// speedup vs baseline: 2.5967x; 1.2382x over previous
#include <cuda_runtime.h>
#include <cuda_bf16.h>
#include <cstdint>

#define BB 16
#define SS 4096
#define DD 64
#define KPP 256
#define SCALE 0.125f

// ---------------- device scratch ----------------
__device__ float g_part8[8 * 2 * 16 * 256 * 64]; // [chunk][proj][b][m256][n64] 16MB
// W as A-operand atoms: [proj][chunk8][stage16][8192]; (m,k32) -> ((m>>3)*4+(k32>>3))*64+(m&7)*8+(k32&7)
__device__ __nv_bfloat16 g_Whi[2 * 8 * 16 * 8192];
__device__ __nv_bfloat16 g_Wlo[2 * 8 * 16 * 8192];
// X as B-operand atoms: [proj][b][chunk8][stage16][2048]; (d,s32) -> ((d>>3)*4+(s32>>3))*64+(d&7)*8+(s32&7)
__device__ __nv_bfloat16 g_Xhi[2 * 16 * 8 * 16 * 2048];
__device__ __nv_bfloat16 g_Xlo[2 * 16 * 8 * 16 * 2048];
// Kp as B-operand atoms for scores: n=kp(256), k=d(64)
__device__ __nv_bfloat16 g_KpBhi[BB * 256 * 64];
__device__ __nv_bfloat16 g_KpBlo[BB * 256 * 64];
// Vp as B-operand atoms for out: n=d(64), k=kp(256)
__device__ __nv_bfloat16 g_VpBhi[BB * 256 * 64];
__device__ __nv_bfloat16 g_VpBlo[BB * 256 * 64];

// ---------------- helpers ----------------
__device__ __forceinline__ uint32_t smem_u32(const void* p) {
    uint32_t a;
    asm("{ .reg .u64 t; cvta.to.shared.u64 t, %1; cvt.u32.u64 %0, t; }" : "=r"(a) : "l"(p));
    return a;
}
__device__ __forceinline__ void ldm_x4(uint32_t* r, uint32_t addr) {
    asm volatile("ldmatrix.sync.aligned.m8n8.x4.shared.b16 {%0,%1,%2,%3}, [%4];"
                 : "=r"(r[0]), "=r"(r[1]), "=r"(r[2]), "=r"(r[3]) : "r"(addr));
}
__device__ __forceinline__ void mma_bf16(float* c, const uint32_t* a, const uint32_t* b) {
    asm volatile(
        "mma.sync.aligned.m16n8k16.row.col.f32.bf16.bf16.f32 "
        "{%0,%1,%2,%3}, {%4,%5,%6,%7}, {%8,%9}, {%0,%1,%2,%3};"
        : "+f"(c[0]), "+f"(c[1]), "+f"(c[2]), "+f"(c[3])
        : "r"(a[0]), "r"(a[1]), "r"(a[2]), "r"(a[3]), "r"(b[0]), "r"(b[1]));
}
__device__ __forceinline__ void sp2(float x, __nv_bfloat16& h, __nv_bfloat16& l) {
    h = __float2bfloat16(x);
    l = __float2bfloat16(x - __bfloat162float(h));
}
__device__ __forceinline__ uint32_t bpk(__nv_bfloat16 a, __nv_bfloat16 b) {
    __nv_bfloat162 t = __halves2bfloat162(a, b);
    return *reinterpret_cast<uint32_t*>(&t);
}
__device__ __forceinline__ void splitpack(float v0, float v1, uint32_t& h, uint32_t& l) {
    __nv_bfloat16 h0, l0, h1, l1;
    sp2(v0, h0, l0);
    sp2(v1, h1, l1);
    h = bpk(h0, h1);
    l = bpk(l0, l1);
}
__device__ __forceinline__ void cpa16(uint32_t dst, const void* src) {
    asm volatile("cp.async.cg.shared.global [%0], [%1], 16;" :: "r"(dst), "l"(src));
}
#define CP_COMMIT asm volatile("cp.async.commit_group;" ::: "memory")
#define CP_WAIT1 asm volatile("cp.async.wait_group 1;" ::: "memory")
#define CP_WAIT0 asm volatile("cp.async.wait_group 0;" ::: "memory")

// ======================================================================
// Kernel 0a: prepack W -> hi/lo A-atoms. grid (16 st, 8 chunk, 2 proj), 256 thr.
// ======================================================================
__global__ __launch_bounds__(256) void prepack_W(const float* __restrict__ Ew,
                                                 const float* __restrict__ Fw) {
    const int st = blockIdx.x, chunk = blockIdx.y, proj = blockIdx.z;
    const int m = threadIdx.x;
    const float* src = (proj ? Fw : Ew) + (size_t)m * SS + chunk * 512 + st * 32;
    const size_t bb = (size_t)((proj * 8 + chunk) * 16 + st) * 8192;

    float4 f[8];
#pragma unroll
    for (int j = 0; j < 8; ++j) f[j] = *(const float4*)(src + j * 4);
#pragma unroll
    for (int kg = 0; kg < 4; ++kg) {
        float v[8] = {f[2 * kg].x, f[2 * kg].y, f[2 * kg].z, f[2 * kg].w,
                      f[2 * kg + 1].x, f[2 * kg + 1].y, f[2 * kg + 1].z, f[2 * kg + 1].w};
        __nv_bfloat16 h[8], l[8];
#pragma unroll
        for (int e = 0; e < 8; ++e) sp2(v[e], h[e], l[e]);
        size_t off = bb + (size_t)(((m >> 3) * 4 + kg) * 64 + (m & 7) * 8);
        *(uint4*)&g_Whi[off] =
            make_uint4(bpk(h[0], h[1]), bpk(h[2], h[3]), bpk(h[4], h[5]), bpk(h[6], h[7]));
        *(uint4*)&g_Wlo[off] =
            make_uint4(bpk(l[0], l[1]), bpk(l[2], l[3]), bpk(l[4], l[5]), bpk(l[6], l[7]));
    }
}

// ======================================================================
// Kernel 0b: prepack X (K,V) -> hi/lo B-atoms. grid (8 chunk, 2 proj, 16 b), 256 thr.
// ======================================================================
__global__ __launch_bounds__(256) void prepack_X(const float* __restrict__ Kin,
                                                 const float* __restrict__ Vin) {
    __shared__ __align__(16) float xs[32][68];
    const int tid = threadIdx.x;
    const int chunk = blockIdx.x, proj = blockIdx.y, b = blockIdx.z;
    const float* X = (proj ? Vin : Kin) + ((size_t)b * SS + chunk * 512) * DD;
    const size_t xb0 = (size_t)(((proj * 16 + b) * 8 + chunk) * 16) * 2048;

    const int d = tid & 63, s8 = tid >> 6;
    for (int st = 0; st < 16; ++st) {
#pragma unroll
        for (int i = 0; i < 2; ++i) {
            int slot = tid + 256 * i;
            int r = slot >> 4, c4 = slot & 15;
            float4 v = *(const float4*)&X[((size_t)st * 32 + r) * DD + c4 * 4];
            *(float4*)&xs[r][c4 * 4] = v;
        }
        __syncthreads();
        __nv_bfloat16 h[8], l[8];
#pragma unroll
        for (int e = 0; e < 8; ++e) sp2(xs[s8 * 8 + e][d], h[e], l[e]);
        size_t off = xb0 + (size_t)st * 2048 + (size_t)(((d >> 3) * 4 + s8) * 64 + (d & 7) * 8);
        *(uint4*)&g_Xhi[off] =
            make_uint4(bpk(h[0], h[1]), bpk(h[2], h[3]), bpk(h[4], h[5]), bpk(h[6], h[7]));
        *(uint4*)&g_Xlo[off] =
            make_uint4(bpk(l[0], l[1]), bpk(l[2], l[3]), bpk(l[4], l[5]), bpk(l[6], l[7]));
        __syncthreads();
    }
}

extern __shared__ __align__(1024) char dsm[];

// ======================================================================
// Kernel 1: projections, cp.async double-buffered, pure-copy staging.
// grid (8 chunk, 2 proj, 16 b), 256 thr, 80KB dyn smem, 2 CTA/SM.
// Buffer layout (bytes, per buf of 40960): Ahi 0, Alo 16384, Bhi 32768, Blo 36864.
// ======================================================================
__global__ __launch_bounds__(256, 2) void proj_mma(const float* __restrict__ dummy) {
    uint32_t smb = smem_u32(dsm);
    const int tid = threadIdx.x, lane = tid & 31, w = tid >> 5;
    const int chunk = blockIdx.x, proj = blockIdx.y, b = blockIdx.z;
    const int wm = w & 3, wn = w >> 2;
    const int b3 = (lane >> 3) & 1, b4 = lane >> 4, r7 = (lane & 7) * 16;

    const uint4* wh0 = (const uint4*)(g_Whi + (size_t)((proj * 8 + chunk) * 16) * 8192);
    const uint4* wl0 = (const uint4*)(g_Wlo + (size_t)((proj * 8 + chunk) * 16) * 8192);
    const uint4* xh0 = (const uint4*)(g_Xhi + (size_t)(((proj * 16 + b) * 8 + chunk) * 16) * 2048);
    const uint4* xl0 = (const uint4*)(g_Xlo + (size_t)(((proj * 16 + b) * 8 + chunk) * 16) * 2048);

    // per-stage uint4 counts: A 1024 each (hi,lo), B 256 each
    auto issue = [&](int st) {
        uint32_t base = smb + (uint32_t)(st & 1) * 40960u;
        const uint4* wh = wh0 + (size_t)st * 1024;
        const uint4* wl = wl0 + (size_t)st * 1024;
        const uint4* xh = xh0 + (size_t)st * 256;
        const uint4* xl = xl0 + (size_t)st * 256;
#pragma unroll
        for (int i = 0; i < 4; ++i)
            cpa16(base + (uint32_t)(tid + 256 * i) * 16u, wh + tid + 256 * i);
#pragma unroll
        for (int i = 0; i < 4; ++i)
            cpa16(base + 16384u + (uint32_t)(tid + 256 * i) * 16u, wl + tid + 256 * i);
        cpa16(base + 32768u + (uint32_t)tid * 16u, xh + tid);
        cpa16(base + 36864u + (uint32_t)tid * 16u, xl + tid);
    };

    float acc[4][4][4];
#pragma unroll
    for (int i = 0; i < 4; ++i)
#pragma unroll
        for (int j = 0; j < 4; ++j)
#pragma unroll
            for (int e = 0; e < 4; ++e) acc[i][j][e] = 0.f;

    issue(0);
    CP_COMMIT;

    for (int st = 0; st < 16; ++st) {
        if (st < 15) {
            issue(st + 1);
            CP_COMMIT;
            CP_WAIT1;
        } else {
            CP_WAIT0;
        }
        __syncthreads();

        const uint32_t bufb = smb + (uint32_t)(st & 1) * 40960u;
        const uint32_t aHi = bufb, aLo = bufb + 16384u;
        const uint32_t bHi = bufb + 32768u, bLo = bufb + 36864u;

#pragma unroll
        for (int kk2 = 0; kk2 < 2; ++kk2) {
            uint32_t ah[4][4], al[4][4], bh[2][4], bl[2][4];
#pragma unroll
            for (int mt = 0; mt < 4; ++mt) {
                uint32_t o = (uint32_t)(((wm * 8 + mt * 2 + b3) * 4 + kk2 * 2 + b4) * 128 + r7);
                ldm_x4(ah[mt], aHi + o);
                ldm_x4(al[mt], aLo + o);
            }
#pragma unroll
            for (int nt2 = 0; nt2 < 2; ++nt2) {
                uint32_t o = (uint32_t)(((wn * 4 + nt2 * 2 + b4) * 4 + kk2 * 2 + b3) * 128 + r7);
                ldm_x4(bh[nt2], bHi + o);
                ldm_x4(bl[nt2], bLo + o);
            }
#pragma unroll
            for (int mt = 0; mt < 4; ++mt)
#pragma unroll
                for (int nt2 = 0; nt2 < 2; ++nt2)
#pragma unroll
                    for (int hf = 0; hf < 2; ++hf) {
                        int nt = nt2 * 2 + hf;
                        mma_bf16(acc[mt][nt], ah[mt], &bh[nt2][hf * 2]);
                        mma_bf16(acc[mt][nt], ah[mt], &bl[nt2][hf * 2]);
                        mma_bf16(acc[mt][nt], al[mt], &bh[nt2][hf * 2]);
                    }
        }
        __syncthreads();
    }

    float* dst = g_part8 + ((size_t)(chunk * 2 + proj) * 16 + b) * 16384;
    const int row = lane >> 2, q2 = (lane & 3) * 2;
#pragma unroll
    for (int mt = 0; mt < 4; ++mt)
#pragma unroll
        for (int nt = 0; nt < 4; ++nt) {
            int m = wm * 64 + mt * 16 + row;
            int n = wn * 32 + nt * 8 + q2;
            *(float2*)&dst[(size_t)m * 64 + n] = make_float2(acc[mt][nt][0], acc[mt][nt][1]);
            *(float2*)&dst[(size_t)(m + 8) * 64 + n] = make_float2(acc[mt][nt][2], acc[mt][nt][3]);
        }
}

// ======================================================================
// Kernel 2: reduce partials + bias -> bf16 hi/lo atom arrays (unchanged R4).
// ======================================================================
__global__ __launch_bounds__(256) void proj_reduce_atoms(const float* __restrict__ Eb,
                                                         const float* __restrict__ Fb) {
    __shared__ float tile[64][65];
    const int tid = threadIdx.x;
    const int kpblk = blockIdx.x, p = blockIdx.y, b = blockIdx.z;

    float4 acc[4] = {make_float4(0, 0, 0, 0), make_float4(0, 0, 0, 0),
                     make_float4(0, 0, 0, 0), make_float4(0, 0, 0, 0)};
#pragma unroll
    for (int c = 0; c < 8; ++c) {
        const float* src = g_part8 + ((size_t)(c * 2 + p) * 16 + b) * 16384 + (size_t)kpblk * 4096;
#pragma unroll
        for (int i = 0; i < 4; ++i) {
            int slot = tid + 256 * i;
            float4 v = *(const float4*)&src[(slot >> 4) * 64 + (slot & 15) * 4];
            acc[i].x += v.x; acc[i].y += v.y; acc[i].z += v.z; acc[i].w += v.w;
        }
    }
    const float* bias = p ? Fb : Eb;
#pragma unroll
    for (int i = 0; i < 4; ++i) {
        int slot = tid + 256 * i;
        int r = slot >> 4, c4 = slot & 15;
        float bv = bias[kpblk * 64 + r];
        tile[r][c4 * 4 + 0] = acc[i].x + bv;
        tile[r][c4 * 4 + 1] = acc[i].y + bv;
        tile[r][c4 * 4 + 2] = acc[i].z + bv;
        tile[r][c4 * 4 + 3] = acc[i].w + bv;
    }
    __syncthreads();

    const int a = tid >> 2, rr0 = (tid & 3) * 2;
    const int g1 = a >> 3, g2 = a & 7;
    if (p == 0) {
        size_t gbase = (size_t)b * 16384 + (size_t)(((kpblk * 8 + g1) * 8 + g2)) * 64;
#pragma unroll
        for (int rr = rr0; rr < rr0 + 2; ++rr) {
            __nv_bfloat16 h[8], l[8];
#pragma unroll
            for (int j = 0; j < 8; ++j) sp2(tile[g1 * 8 + rr][g2 * 8 + j], h[j], l[j]);
            *(uint4*)&g_KpBhi[gbase + rr * 8] =
                make_uint4(bpk(h[0], h[1]), bpk(h[2], h[3]), bpk(h[4], h[5]), bpk(h[6], h[7]));
            *(uint4*)&g_KpBlo[gbase + rr * 8] =
                make_uint4(bpk(l[0], l[1]), bpk(l[2], l[3]), bpk(l[4], l[5]), bpk(l[6], l[7]));
        }
    } else {
        size_t gbase = (size_t)b * 16384 + (size_t)((g1 * 32 + kpblk * 8 + g2)) * 64;
#pragma unroll
        for (int rr = rr0; rr < rr0 + 2; ++rr) {
            __nv_bfloat16 h[8], l[8];
#pragma unroll
            for (int j = 0; j < 8; ++j) sp2(tile[g2 * 8 + j][g1 * 8 + rr], h[j], l[j]);
            *(uint4*)&g_VpBhi[gbase + rr * 8] =
                make_uint4(bpk(h[0], h[1]), bpk(h[2], h[3]), bpk(h[4], h[5]), bpk(h[6], h[7]));
            *(uint4*)&g_VpBlo[gbase + rr * 8] =
                make_uint4(bpk(l[0], l[1]), bpk(l[2], l[3]), bpk(l[4], l[5]), bpk(l[6], l[7]));
        }
    }
}

// ======================================================================
// Kernel 3: fused attention (validated R4; staging now cp.async).
// ======================================================================
#define AT_QHI 0
#define AT_QLO 8192
#define AT_KHI 16384
#define AT_KLO 49152
#define AT_VHI 81920
#define AT_VLO 114688
#define AT_ORED 147456
#define AT_MAX 164352
#define AT_SUM 164864
#define AT_SMEM 165376

__global__ __launch_bounds__(256, 1) void attn_fused(const float* __restrict__ Q,
                                                     float* __restrict__ attnp,
                                                     float* __restrict__ outp) {
    uint32_t smb = smem_u32(dsm);
    const int tid = threadIdx.x, lane = tid & 31, w = tid >> 5;
    const int b = blockIdx.y, s0 = blockIdx.x * 64;

    // ---- stage Kp/Vp atom arrays via cp.async ----
    {
        const uint4* kh = (const uint4*)(g_KpBhi + (size_t)b * 16384);
        const uint4* kl = (const uint4*)(g_KpBlo + (size_t)b * 16384);
        const uint4* vh = (const uint4*)(g_VpBhi + (size_t)b * 16384);
        const uint4* vl = (const uint4*)(g_VpBlo + (size_t)b * 16384);
#pragma unroll
        for (int i = 0; i < 8; ++i) {
            uint32_t s = (uint32_t)(tid + 256 * i);
            cpa16(smb + AT_KHI + s * 16, kh + s);
            cpa16(smb + AT_KLO + s * 16, kl + s);
            cpa16(smb + AT_VHI + s * 16, vh + s);
            cpa16(smb + AT_VLO + s * 16, vl + s);
        }
        CP_COMMIT;
    }
    // ---- build Q A-atoms (scale folded) while copies fly ----
    {
        const float* Qb = Q + ((size_t)b * SS + s0) * DD;
        __nv_bfloat16* qh = (__nv_bfloat16*)(dsm + AT_QHI);
        __nv_bfloat16* ql = (__nv_bfloat16*)(dsm + AT_QLO);
#pragma unroll
        for (int i = 0; i < 4; ++i) {
            int slot = tid + 256 * i;
            int r = slot >> 4, d4 = slot & 15;
            float4 v = *(const float4*)&Qb[(size_t)r * DD + d4 * 4];
            __nv_bfloat16 h0, h1, h2, h3, l0, l1, l2, l3;
            sp2(v.x * SCALE, h0, l0);
            sp2(v.y * SCALE, h1, l1);
            sp2(v.z * SCALE, h2, l2);
            sp2(v.w * SCALE, h3, l3);
            int off = ((r >> 3) * 8 + (d4 >> 1)) * 64 + (r & 7) * 8 + (d4 & 1) * 4;
            *(uint2*)&qh[off] = make_uint2(bpk(h0, h1), bpk(h2, h3));
            *(uint2*)&ql[off] = make_uint2(bpk(l0, l1), bpk(l2, l3));
        }
    }
    CP_WAIT0;
    __syncthreads();

    const int wm = w >> 1, wnh = w & 1;
    const int b3 = (lane >> 3) & 1, b4 = lane >> 4, r7 = (lane & 7) * 16;
    const uint32_t qhi = smb + AT_QHI, qlo = smb + AT_QLO;
    const uint32_t kphi = smb + AT_KHI, kplo = smb + AT_KLO;
    const uint32_t vphi = smb + AT_VHI, vplo = smb + AT_VLO;

    float c[16][4];
#pragma unroll
    for (int i = 0; i < 16; ++i)
#pragma unroll
        for (int e = 0; e < 4; ++e) c[i][e] = 0.f;

#pragma unroll
    for (int kk = 0; kk < 4; ++kk) {
        uint32_t ah[4], al[4];
        uint32_t oA = (uint32_t)(((wm * 2 + b3) * 8 + kk * 2 + b4) * 128 + r7);
        ldm_x4(ah, qhi + oA);
        ldm_x4(al, qlo + oA);
#pragma unroll
        for (int nt2 = 0; nt2 < 8; ++nt2) {
            uint32_t bh[4], bl[4];
            uint32_t oB = (uint32_t)(((wnh * 16 + nt2 * 2 + b4) * 8 + kk * 2 + b3) * 128 + r7);
            ldm_x4(bh, kphi + oB);
            ldm_x4(bl, kplo + oB);
#pragma unroll
            for (int hf = 0; hf < 2; ++hf) {
                int nt = nt2 * 2 + hf;
                mma_bf16(c[nt], ah, &bh[hf * 2]);
                mma_bf16(c[nt], ah, &bl[hf * 2]);
                mma_bf16(c[nt], al, &bh[hf * 2]);
            }
        }
    }

    const int rl = wm * 16 + (lane >> 2);
    float* smax = (float*)(dsm + AT_MAX);
    float* ssum = (float*)(dsm + AT_SUM);

    float m0 = -1e30f, m1 = -1e30f;
#pragma unroll
    for (int nt = 0; nt < 16; ++nt) {
        m0 = fmaxf(m0, fmaxf(c[nt][0], c[nt][1]));
        m1 = fmaxf(m1, fmaxf(c[nt][2], c[nt][3]));
    }
#pragma unroll
    for (int off = 1; off <= 2; off <<= 1) {
        m0 = fmaxf(m0, __shfl_xor_sync(0xffffffffu, m0, off));
        m1 = fmaxf(m1, __shfl_xor_sync(0xffffffffu, m1, off));
    }
    if ((lane & 3) == 0) {
        smax[wnh * 64 + rl] = m0;
        smax[wnh * 64 + rl + 8] = m1;
    }
    __syncthreads();
    m0 = fmaxf(m0, smax[(wnh ^ 1) * 64 + rl]);
    m1 = fmaxf(m1, smax[(wnh ^ 1) * 64 + rl + 8]);

    float s0a = 0.f, s1a = 0.f;
#pragma unroll
    for (int nt = 0; nt < 16; ++nt) {
        c[nt][0] = __expf(c[nt][0] - m0);
        c[nt][1] = __expf(c[nt][1] - m0);
        c[nt][2] = __expf(c[nt][2] - m1);
        c[nt][3] = __expf(c[nt][3] - m1);
        s0a += c[nt][0] + c[nt][1];
        s1a += c[nt][2] + c[nt][3];
    }
#pragma unroll
    for (int off = 1; off <= 2; off <<= 1) {
        s0a += __shfl_xor_sync(0xffffffffu, s0a, off);
        s1a += __shfl_xor_sync(0xffffffffu, s1a, off);
    }
    if ((lane & 3) == 0) {
        ssum[wnh * 64 + rl] = s0a;
        ssum[wnh * 64 + rl + 8] = s1a;
    }
    __syncthreads();
    float inv0 = 1.f / (s0a + ssum[(wnh ^ 1) * 64 + rl]);
    float inv1 = 1.f / (s1a + ssum[(wnh ^ 1) * 64 + rl + 8]);

    float* abase = attnp + ((size_t)b * SS + s0 + rl) * KPP + wnh * 128 + (lane & 3) * 2;
#pragma unroll
    for (int nt = 0; nt < 16; ++nt) {
        c[nt][0] *= inv0;
        c[nt][1] *= inv0;
        c[nt][2] *= inv1;
        c[nt][3] *= inv1;
        *(float2*)&abase[nt * 8] = make_float2(c[nt][0], c[nt][1]);
        *(float2*)&abase[8 * KPP + nt * 8] = make_float2(c[nt][2], c[nt][3]);
    }

    float oc[8][4];
#pragma unroll
    for (int i = 0; i < 8; ++i)
#pragma unroll
        for (int e = 0; e < 4; ++e) oc[i][e] = 0.f;

#pragma unroll
    for (int t2 = 0; t2 < 8; ++t2) {
        uint32_t pah[4], pal[4];
        splitpack(c[2 * t2][0], c[2 * t2][1], pah[0], pal[0]);
        splitpack(c[2 * t2][2], c[2 * t2][3], pah[1], pal[1]);
        splitpack(c[2 * t2 + 1][0], c[2 * t2 + 1][1], pah[2], pal[2]);
        splitpack(c[2 * t2 + 1][2], c[2 * t2 + 1][3], pah[3], pal[3]);
#pragma unroll
        for (int nt2 = 0; nt2 < 4; ++nt2) {
            uint32_t vh[4], vl[4];
            uint32_t oV = (uint32_t)(((nt2 * 2 + b4) * 32 + wnh * 16 + t2 * 2 + b3) * 128 + r7);
            ldm_x4(vh, vphi + oV);
            ldm_x4(vl, vplo + oV);
#pragma unroll
            for (int hf = 0; hf < 2; ++hf) {
                int nt = nt2 * 2 + hf;
                mma_bf16(oc[nt], pah, &vh[hf * 2]);
                mma_bf16(oc[nt], pah, &vl[hf * 2]);
                mma_bf16(oc[nt], pal, &vh[hf * 2]);
            }
        }
    }

    float* Ored = (float*)(dsm + AT_ORED);
    if (wnh == 1) {
#pragma unroll
        for (int nt = 0; nt < 8; ++nt) {
            int col = nt * 8 + (lane & 3) * 2;
            *(float2*)&Ored[rl * 66 + col] = make_float2(oc[nt][0], oc[nt][1]);
            *(float2*)&Ored[(rl + 8) * 66 + col] = make_float2(oc[nt][2], oc[nt][3]);
        }
    }
    __syncthreads();
    if (wnh == 0) {
        float* o0 = outp + ((size_t)b * SS + s0 + rl) * DD;
#pragma unroll
        for (int nt = 0; nt < 8; ++nt) {
            int col = nt * 8 + (lane & 3) * 2;
            float2 r0v = *(float2*)&Ored[rl * 66 + col];
            float2 r1v = *(float2*)&Ored[(rl + 8) * 66 + col];
            *(float2*)&o0[col] = make_float2(oc[nt][0] + r0v.x, oc[nt][1] + r0v.y);
            *(float2*)&o0[8 * DD + col] = make_float2(oc[nt][2] + r1v.x, oc[nt][3] + r1v.y);
        }
    }
}

// ======================================================================
extern "C" void kernel_launch(void* const* d_in, const int* in_sizes, int n_in,
                              void* d_out, int out_size) {
    const float* Q  = (const float*)d_in[0];
    const float* K  = (const float*)d_in[1];
    const float* V  = (const float*)d_in[2];
    const float* Ew = (const float*)d_in[3];
    const float* Eb = (const float*)d_in[4];
    const float* Fw = (const float*)d_in[5];
    const float* Fb = (const float*)d_in[6];

    float* outp  = (float*)d_out;
    float* attnp = outp + (size_t)BB * SS * DD;

    cudaFuncSetAttribute(proj_mma, cudaFuncAttributeMaxDynamicSharedMemorySize, 81920);
    cudaFuncSetAttribute(attn_fused, cudaFuncAttributeMaxDynamicSharedMemorySize, AT_SMEM);

    prepack_W<<<dim3(16, 8, 2), 256>>>(Ew, Fw);
    prepack_X<<<dim3(8, 2, BB), 256>>>(K, V);
    proj_mma<<<dim3(8, 2, BB), 256, 81920>>>(Q);
    proj_reduce_atoms<<<dim3(4, 2, BB), 256>>>(Eb, Fb);
    attn_fused<<<dim3(SS / 64, BB), 256, AT_SMEM>>>(Q, attnp, outp);
}

// round 6
// speedup vs baseline: 2.9474x; 1.1350x over previous
#include <cuda_runtime.h>
#include <cuda_bf16.h>
#include <cuda_fp16.h>
#include <cstdint>

#define BB 16
#define SS 4096
#define DD 64
#define KPP 256
#define SCALE 0.125f

// ---------------- device scratch ----------------
__device__ float g_part8[8 * 2 * 16 * 256 * 64]; // [chunk][proj][b][m256][n64] 16MB
// W as A-operand atoms (bf16 hi/lo, validated)
__device__ __nv_bfloat16 g_Whi[2 * 8 * 16 * 8192];
__device__ __nv_bfloat16 g_Wlo[2 * 8 * 16 * 8192];
// X as B-operand atoms (bf16 hi/lo, validated)
__device__ __nv_bfloat16 g_Xhi[2 * 16 * 8 * 16 * 2048];
__device__ __nv_bfloat16 g_Xlo[2 * 16 * 8 * 16 * 2048];
// Kp/Vp as SINGLE fp16 B-operand atoms (R6: 2-term scheme)
__device__ __half g_KpH[BB * 256 * 64];
__device__ __half g_VpH[BB * 256 * 64];

// ---------------- helpers ----------------
__device__ __forceinline__ uint32_t smem_u32(const void* p) {
    uint32_t a;
    asm("{ .reg .u64 t; cvta.to.shared.u64 t, %1; cvt.u32.u64 %0, t; }" : "=r"(a) : "l"(p));
    return a;
}
__device__ __forceinline__ void ldm_x4(uint32_t* r, uint32_t addr) {
    asm volatile("ldmatrix.sync.aligned.m8n8.x4.shared.b16 {%0,%1,%2,%3}, [%4];"
                 : "=r"(r[0]), "=r"(r[1]), "=r"(r[2]), "=r"(r[3]) : "r"(addr));
}
__device__ __forceinline__ void mma_bf16(float* c, const uint32_t* a, const uint32_t* b) {
    asm volatile(
        "mma.sync.aligned.m16n8k16.row.col.f32.bf16.bf16.f32 "
        "{%0,%1,%2,%3}, {%4,%5,%6,%7}, {%8,%9}, {%0,%1,%2,%3};"
        : "+f"(c[0]), "+f"(c[1]), "+f"(c[2]), "+f"(c[3])
        : "r"(a[0]), "r"(a[1]), "r"(a[2]), "r"(a[3]), "r"(b[0]), "r"(b[1]));
}
__device__ __forceinline__ void mma_fp16(float* c, const uint32_t* a, const uint32_t* b) {
    asm volatile(
        "mma.sync.aligned.m16n8k16.row.col.f32.f16.f16.f32 "
        "{%0,%1,%2,%3}, {%4,%5,%6,%7}, {%8,%9}, {%0,%1,%2,%3};"
        : "+f"(c[0]), "+f"(c[1]), "+f"(c[2]), "+f"(c[3])
        : "r"(a[0]), "r"(a[1]), "r"(a[2]), "r"(a[3]), "r"(b[0]), "r"(b[1]));
}
__device__ __forceinline__ void sp2(float x, __nv_bfloat16& h, __nv_bfloat16& l) {
    h = __float2bfloat16(x);
    l = __float2bfloat16(x - __bfloat162float(h));
}
__device__ __forceinline__ uint32_t bpk(__nv_bfloat16 a, __nv_bfloat16 b) {
    __nv_bfloat162 t = __halves2bfloat162(a, b);
    return *reinterpret_cast<uint32_t*>(&t);
}
__device__ __forceinline__ void sp2h(float x, __half& h, __half& l) {
    h = __float2half(x);
    l = __float2half(x - __half2float(h));
}
__device__ __forceinline__ uint32_t hpk(__half a, __half b) {
    __half2 t = __halves2half2(a, b);
    return *reinterpret_cast<uint32_t*>(&t);
}
__device__ __forceinline__ void splitpackh(float v0, float v1, uint32_t& h, uint32_t& l) {
    __half h0, l0, h1, l1;
    sp2h(v0, h0, l0);
    sp2h(v1, h1, l1);
    h = hpk(h0, h1);
    l = hpk(l0, l1);
}
__device__ __forceinline__ void cpa16(uint32_t dst, const void* src) {
    asm volatile("cp.async.cg.shared.global [%0], [%1], 16;" :: "r"(dst), "l"(src));
}
#define CP_COMMIT asm volatile("cp.async.commit_group;" ::: "memory")
#define CP_WAIT1 asm volatile("cp.async.wait_group 1;" ::: "memory")
#define CP_WAIT0 asm volatile("cp.async.wait_group 0;" ::: "memory")

// ======================================================================
// Kernel 0a: prepack W -> hi/lo A-atoms (unchanged).
// ======================================================================
__global__ __launch_bounds__(256) void prepack_W(const float* __restrict__ Ew,
                                                 const float* __restrict__ Fw) {
    const int st = blockIdx.x, chunk = blockIdx.y, proj = blockIdx.z;
    const int m = threadIdx.x;
    const float* src = (proj ? Fw : Ew) + (size_t)m * SS + chunk * 512 + st * 32;
    const size_t bb = (size_t)((proj * 8 + chunk) * 16 + st) * 8192;

    float4 f[8];
#pragma unroll
    for (int j = 0; j < 8; ++j) f[j] = *(const float4*)(src + j * 4);
#pragma unroll
    for (int kg = 0; kg < 4; ++kg) {
        float v[8] = {f[2 * kg].x, f[2 * kg].y, f[2 * kg].z, f[2 * kg].w,
                      f[2 * kg + 1].x, f[2 * kg + 1].y, f[2 * kg + 1].z, f[2 * kg + 1].w};
        __nv_bfloat16 h[8], l[8];
#pragma unroll
        for (int e = 0; e < 8; ++e) sp2(v[e], h[e], l[e]);
        size_t off = bb + (size_t)(((m >> 3) * 4 + kg) * 64 + (m & 7) * 8);
        *(uint4*)&g_Whi[off] =
            make_uint4(bpk(h[0], h[1]), bpk(h[2], h[3]), bpk(h[4], h[5]), bpk(h[6], h[7]));
        *(uint4*)&g_Wlo[off] =
            make_uint4(bpk(l[0], l[1]), bpk(l[2], l[3]), bpk(l[4], l[5]), bpk(l[6], l[7]));
    }
}

// ======================================================================
// Kernel 0b: prepack X -> hi/lo B-atoms (unchanged).
// ======================================================================
__global__ __launch_bounds__(256) void prepack_X(const float* __restrict__ Kin,
                                                 const float* __restrict__ Vin) {
    __shared__ __align__(16) float xs[32][68];
    const int tid = threadIdx.x;
    const int chunk = blockIdx.x, proj = blockIdx.y, b = blockIdx.z;
    const float* X = (proj ? Vin : Kin) + ((size_t)b * SS + chunk * 512) * DD;
    const size_t xb0 = (size_t)(((proj * 16 + b) * 8 + chunk) * 16) * 2048;

    const int d = tid & 63, s8 = tid >> 6;
    for (int st = 0; st < 16; ++st) {
#pragma unroll
        for (int i = 0; i < 2; ++i) {
            int slot = tid + 256 * i;
            int r = slot >> 4, c4 = slot & 15;
            float4 v = *(const float4*)&X[((size_t)st * 32 + r) * DD + c4 * 4];
            *(float4*)&xs[r][c4 * 4] = v;
        }
        __syncthreads();
        __nv_bfloat16 h[8], l[8];
#pragma unroll
        for (int e = 0; e < 8; ++e) sp2(xs[s8 * 8 + e][d], h[e], l[e]);
        size_t off = xb0 + (size_t)st * 2048 + (size_t)(((d >> 3) * 4 + s8) * 64 + (d & 7) * 8);
        *(uint4*)&g_Xhi[off] =
            make_uint4(bpk(h[0], h[1]), bpk(h[2], h[3]), bpk(h[4], h[5]), bpk(h[6], h[7]));
        *(uint4*)&g_Xlo[off] =
            make_uint4(bpk(l[0], l[1]), bpk(l[2], l[3]), bpk(l[4], l[5]), bpk(l[6], l[7]));
        __syncthreads();
    }
}

extern __shared__ __align__(1024) char dsm[];

// ======================================================================
// Kernel 1: projections (unchanged R5, validated).
// ======================================================================
__global__ __launch_bounds__(256, 2) void proj_mma(const float* __restrict__ dummy) {
    uint32_t smb = smem_u32(dsm);
    const int tid = threadIdx.x, lane = tid & 31, w = tid >> 5;
    const int chunk = blockIdx.x, proj = blockIdx.y, b = blockIdx.z;
    const int wm = w & 3, wn = w >> 2;
    const int b3 = (lane >> 3) & 1, b4 = lane >> 4, r7 = (lane & 7) * 16;

    const uint4* wh0 = (const uint4*)(g_Whi + (size_t)((proj * 8 + chunk) * 16) * 8192);
    const uint4* wl0 = (const uint4*)(g_Wlo + (size_t)((proj * 8 + chunk) * 16) * 8192);
    const uint4* xh0 = (const uint4*)(g_Xhi + (size_t)(((proj * 16 + b) * 8 + chunk) * 16) * 2048);
    const uint4* xl0 = (const uint4*)(g_Xlo + (size_t)(((proj * 16 + b) * 8 + chunk) * 16) * 2048);

    auto issue = [&](int st) {
        uint32_t base = smb + (uint32_t)(st & 1) * 40960u;
        const uint4* wh = wh0 + (size_t)st * 1024;
        const uint4* wl = wl0 + (size_t)st * 1024;
        const uint4* xh = xh0 + (size_t)st * 256;
        const uint4* xl = xl0 + (size_t)st * 256;
#pragma unroll
        for (int i = 0; i < 4; ++i)
            cpa16(base + (uint32_t)(tid + 256 * i) * 16u, wh + tid + 256 * i);
#pragma unroll
        for (int i = 0; i < 4; ++i)
            cpa16(base + 16384u + (uint32_t)(tid + 256 * i) * 16u, wl + tid + 256 * i);
        cpa16(base + 32768u + (uint32_t)tid * 16u, xh + tid);
        cpa16(base + 36864u + (uint32_t)tid * 16u, xl + tid);
    };

    float acc[4][4][4];
#pragma unroll
    for (int i = 0; i < 4; ++i)
#pragma unroll
        for (int j = 0; j < 4; ++j)
#pragma unroll
            for (int e = 0; e < 4; ++e) acc[i][j][e] = 0.f;

    issue(0);
    CP_COMMIT;

    for (int st = 0; st < 16; ++st) {
        if (st < 15) {
            issue(st + 1);
            CP_COMMIT;
            CP_WAIT1;
        } else {
            CP_WAIT0;
        }
        __syncthreads();

        const uint32_t bufb = smb + (uint32_t)(st & 1) * 40960u;
        const uint32_t aHi = bufb, aLo = bufb + 16384u;
        const uint32_t bHi = bufb + 32768u, bLo = bufb + 36864u;

#pragma unroll
        for (int kk2 = 0; kk2 < 2; ++kk2) {
            uint32_t ah[4][4], al[4][4], bh[2][4], bl[2][4];
#pragma unroll
            for (int mt = 0; mt < 4; ++mt) {
                uint32_t o = (uint32_t)(((wm * 8 + mt * 2 + b3) * 4 + kk2 * 2 + b4) * 128 + r7);
                ldm_x4(ah[mt], aHi + o);
                ldm_x4(al[mt], aLo + o);
            }
#pragma unroll
            for (int nt2 = 0; nt2 < 2; ++nt2) {
                uint32_t o = (uint32_t)(((wn * 4 + nt2 * 2 + b4) * 4 + kk2 * 2 + b3) * 128 + r7);
                ldm_x4(bh[nt2], bHi + o);
                ldm_x4(bl[nt2], bLo + o);
            }
#pragma unroll
            for (int mt = 0; mt < 4; ++mt)
#pragma unroll
                for (int nt2 = 0; nt2 < 2; ++nt2)
#pragma unroll
                    for (int hf = 0; hf < 2; ++hf) {
                        int nt = nt2 * 2 + hf;
                        mma_bf16(acc[mt][nt], ah[mt], &bh[nt2][hf * 2]);
                        mma_bf16(acc[mt][nt], ah[mt], &bl[nt2][hf * 2]);
                        mma_bf16(acc[mt][nt], al[mt], &bh[nt2][hf * 2]);
                    }
        }
        __syncthreads();
    }

    float* dst = g_part8 + ((size_t)(chunk * 2 + proj) * 16 + b) * 16384;
    const int row = lane >> 2, q2 = (lane & 3) * 2;
#pragma unroll
    for (int mt = 0; mt < 4; ++mt)
#pragma unroll
        for (int nt = 0; nt < 4; ++nt) {
            int m = wm * 64 + mt * 16 + row;
            int n = wn * 32 + nt * 8 + q2;
            *(float2*)&dst[(size_t)m * 64 + n] = make_float2(acc[mt][nt][0], acc[mt][nt][1]);
            *(float2*)&dst[(size_t)(m + 8) * 64 + n] = make_float2(acc[mt][nt][2], acc[mt][nt][3]);
        }
}

// ======================================================================
// Kernel 2: reduce partials + bias -> SINGLE fp16 atom arrays.
// ======================================================================
__global__ __launch_bounds__(256) void proj_reduce_atoms(const float* __restrict__ Eb,
                                                         const float* __restrict__ Fb) {
    __shared__ float tile[64][65];
    const int tid = threadIdx.x;
    const int kpblk = blockIdx.x, p = blockIdx.y, b = blockIdx.z;

    float4 acc[4] = {make_float4(0, 0, 0, 0), make_float4(0, 0, 0, 0),
                     make_float4(0, 0, 0, 0), make_float4(0, 0, 0, 0)};
#pragma unroll
    for (int c = 0; c < 8; ++c) {
        const float* src = g_part8 + ((size_t)(c * 2 + p) * 16 + b) * 16384 + (size_t)kpblk * 4096;
#pragma unroll
        for (int i = 0; i < 4; ++i) {
            int slot = tid + 256 * i;
            float4 v = *(const float4*)&src[(slot >> 4) * 64 + (slot & 15) * 4];
            acc[i].x += v.x; acc[i].y += v.y; acc[i].z += v.z; acc[i].w += v.w;
        }
    }
    const float* bias = p ? Fb : Eb;
#pragma unroll
    for (int i = 0; i < 4; ++i) {
        int slot = tid + 256 * i;
        int r = slot >> 4, c4 = slot & 15;
        float bv = bias[kpblk * 64 + r];
        tile[r][c4 * 4 + 0] = acc[i].x + bv;
        tile[r][c4 * 4 + 1] = acc[i].y + bv;
        tile[r][c4 * 4 + 2] = acc[i].z + bv;
        tile[r][c4 * 4 + 3] = acc[i].w + bv;
    }
    __syncthreads();

    const int a = tid >> 2, rr0 = (tid & 3) * 2;
    const int g1 = a >> 3, g2 = a & 7;
    if (p == 0) {
        // Kp atoms: n8 = kp group (kpblk*8+g1), k8 = d group (g2)
        size_t gbase = (size_t)b * 16384 + (size_t)(((kpblk * 8 + g1) * 8 + g2)) * 64;
#pragma unroll
        for (int rr = rr0; rr < rr0 + 2; ++rr) {
            __half h[8];
#pragma unroll
            for (int j = 0; j < 8; ++j) h[j] = __float2half(tile[g1 * 8 + rr][g2 * 8 + j]);
            *(uint4*)&g_KpH[gbase + rr * 8] =
                make_uint4(hpk(h[0], h[1]), hpk(h[2], h[3]), hpk(h[4], h[5]), hpk(h[6], h[7]));
        }
    } else {
        // Vp atoms: n8 = d group (g1), k8 = kp group (kpblk*8+g2)
        size_t gbase = (size_t)b * 16384 + (size_t)((g1 * 32 + kpblk * 8 + g2)) * 64;
#pragma unroll
        for (int rr = rr0; rr < rr0 + 2; ++rr) {
            __half h[8];
#pragma unroll
            for (int j = 0; j < 8; ++j) h[j] = __float2half(tile[g2 * 8 + j][g1 * 8 + rr]);
            *(uint4*)&g_VpH[gbase + rr * 8] =
                make_uint4(hpk(h[0], h[1]), hpk(h[2], h[3]), hpk(h[4], h[5]), hpk(h[6], h[7]));
        }
    }
}

// ======================================================================
// Kernel 3: fused attention, 2-term fp16. 97.5KB smem, 2 CTA/SM.
// ======================================================================
#define AT_QHI 0
#define AT_QLO 8192
#define AT_KP 16384
#define AT_VP 49152
#define AT_ORED 81920
#define AT_MAX 98816
#define AT_SUM 99328
#define AT_SMEM 99840

__global__ __launch_bounds__(256, 2) void attn_fused(const float* __restrict__ Q,
                                                     float* __restrict__ attnp,
                                                     float* __restrict__ outp) {
    uint32_t smb = smem_u32(dsm);
    const int tid = threadIdx.x, lane = tid & 31, w = tid >> 5;
    const int b = blockIdx.y, s0 = blockIdx.x * 64;

    // ---- stage Kp/Vp fp16 atoms via cp.async ----
    {
        const uint4* kh = (const uint4*)(g_KpH + (size_t)b * 16384);
        const uint4* vh = (const uint4*)(g_VpH + (size_t)b * 16384);
#pragma unroll
        for (int i = 0; i < 8; ++i) {
            uint32_t s = (uint32_t)(tid + 256 * i);
            cpa16(smb + AT_KP + s * 16, kh + s);
            cpa16(smb + AT_VP + s * 16, vh + s);
        }
        CP_COMMIT;
    }
    // ---- build Q fp16 hi/lo A-atoms (scale folded) while copies fly ----
    {
        const float* Qb = Q + ((size_t)b * SS + s0) * DD;
        __half* qh = (__half*)(dsm + AT_QHI);
        __half* ql = (__half*)(dsm + AT_QLO);
#pragma unroll
        for (int i = 0; i < 4; ++i) {
            int slot = tid + 256 * i;
            int r = slot >> 4, d4 = slot & 15;
            float4 v = *(const float4*)&Qb[(size_t)r * DD + d4 * 4];
            __half h0, h1, h2, h3, l0, l1, l2, l3;
            sp2h(v.x * SCALE, h0, l0);
            sp2h(v.y * SCALE, h1, l1);
            sp2h(v.z * SCALE, h2, l2);
            sp2h(v.w * SCALE, h3, l3);
            int off = ((r >> 3) * 8 + (d4 >> 1)) * 64 + (r & 7) * 8 + (d4 & 1) * 4;
            *(uint2*)&qh[off] = make_uint2(hpk(h0, h1), hpk(h2, h3));
            *(uint2*)&ql[off] = make_uint2(hpk(l0, l1), hpk(l2, l3));
        }
    }
    CP_WAIT0;
    __syncthreads();

    const int wm = w >> 1, wnh = w & 1;
    const int b3 = (lane >> 3) & 1, b4 = lane >> 4, r7 = (lane & 7) * 16;
    const uint32_t qhi = smb + AT_QHI, qlo = smb + AT_QLO;
    const uint32_t kp = smb + AT_KP, vp = smb + AT_VP;

    // ---- scores: (Qh+Ql) @ Kp(fp16) ----
    float c[16][4];
#pragma unroll
    for (int i = 0; i < 16; ++i)
#pragma unroll
        for (int e = 0; e < 4; ++e) c[i][e] = 0.f;

#pragma unroll
    for (int kk = 0; kk < 4; ++kk) {
        uint32_t ah[4], al[4];
        uint32_t oA = (uint32_t)(((wm * 2 + b3) * 8 + kk * 2 + b4) * 128 + r7);
        ldm_x4(ah, qhi + oA);
        ldm_x4(al, qlo + oA);
#pragma unroll
        for (int nt2 = 0; nt2 < 8; ++nt2) {
            uint32_t bf[4];
            uint32_t oB = (uint32_t)(((wnh * 16 + nt2 * 2 + b4) * 8 + kk * 2 + b3) * 128 + r7);
            ldm_x4(bf, kp + oB);
#pragma unroll
            for (int hf = 0; hf < 2; ++hf) {
                int nt = nt2 * 2 + hf;
                mma_fp16(c[nt], ah, &bf[hf * 2]);
                mma_fp16(c[nt], al, &bf[hf * 2]);
            }
        }
    }

    // ---- softmax over 256 (two warp-halves joined via smem) ----
    const int rl = wm * 16 + (lane >> 2);
    float* smax = (float*)(dsm + AT_MAX);
    float* ssum = (float*)(dsm + AT_SUM);

    float m0 = -1e30f, m1 = -1e30f;
#pragma unroll
    for (int nt = 0; nt < 16; ++nt) {
        m0 = fmaxf(m0, fmaxf(c[nt][0], c[nt][1]));
        m1 = fmaxf(m1, fmaxf(c[nt][2], c[nt][3]));
    }
#pragma unroll
    for (int off = 1; off <= 2; off <<= 1) {
        m0 = fmaxf(m0, __shfl_xor_sync(0xffffffffu, m0, off));
        m1 = fmaxf(m1, __shfl_xor_sync(0xffffffffu, m1, off));
    }
    if ((lane & 3) == 0) {
        smax[wnh * 64 + rl] = m0;
        smax[wnh * 64 + rl + 8] = m1;
    }
    __syncthreads();
    m0 = fmaxf(m0, smax[(wnh ^ 1) * 64 + rl]);
    m1 = fmaxf(m1, smax[(wnh ^ 1) * 64 + rl + 8]);

    float s0a = 0.f, s1a = 0.f;
#pragma unroll
    for (int nt = 0; nt < 16; ++nt) {
        c[nt][0] = __expf(c[nt][0] - m0);
        c[nt][1] = __expf(c[nt][1] - m0);
        c[nt][2] = __expf(c[nt][2] - m1);
        c[nt][3] = __expf(c[nt][3] - m1);
        s0a += c[nt][0] + c[nt][1];
        s1a += c[nt][2] + c[nt][3];
    }
#pragma unroll
    for (int off = 1; off <= 2; off <<= 1) {
        s0a += __shfl_xor_sync(0xffffffffu, s0a, off);
        s1a += __shfl_xor_sync(0xffffffffu, s1a, off);
    }
    if ((lane & 3) == 0) {
        ssum[wnh * 64 + rl] = s0a;
        ssum[wnh * 64 + rl + 8] = s1a;
    }
    __syncthreads();
    float inv0 = 1.f / (s0a + ssum[(wnh ^ 1) * 64 + rl]);
    float inv1 = 1.f / (s1a + ssum[(wnh ^ 1) * 64 + rl + 8]);

    // ---- scale probs + write attn ----
    float* abase = attnp + ((size_t)b * SS + s0 + rl) * KPP + wnh * 128 + (lane & 3) * 2;
#pragma unroll
    for (int nt = 0; nt < 16; ++nt) {
        c[nt][0] *= inv0;
        c[nt][1] *= inv0;
        c[nt][2] *= inv1;
        c[nt][3] *= inv1;
        *(float2*)&abase[nt * 8] = make_float2(c[nt][0], c[nt][1]);
        *(float2*)&abase[8 * KPP + nt * 8] = make_float2(c[nt][2], c[nt][3]);
    }

    // ---- out GEMM: (Ph+Pl) @ Vp(fp16), k-half per warp ----
    float oc[8][4];
#pragma unroll
    for (int i = 0; i < 8; ++i)
#pragma unroll
        for (int e = 0; e < 4; ++e) oc[i][e] = 0.f;

#pragma unroll
    for (int t2 = 0; t2 < 8; ++t2) {
        uint32_t pah[4], pal[4];
        splitpackh(c[2 * t2][0], c[2 * t2][1], pah[0], pal[0]);
        splitpackh(c[2 * t2][2], c[2 * t2][3], pah[1], pal[1]);
        splitpackh(c[2 * t2 + 1][0], c[2 * t2 + 1][1], pah[2], pal[2]);
        splitpackh(c[2 * t2 + 1][2], c[2 * t2 + 1][3], pah[3], pal[3]);
#pragma unroll
        for (int nt2 = 0; nt2 < 4; ++nt2) {
            uint32_t vf[4];
            uint32_t oV = (uint32_t)(((nt2 * 2 + b4) * 32 + wnh * 16 + t2 * 2 + b3) * 128 + r7);
            ldm_x4(vf, vp + oV);
#pragma unroll
            for (int hf = 0; hf < 2; ++hf) {
                int nt = nt2 * 2 + hf;
                mma_fp16(oc[nt], pah, &vf[hf * 2]);
                mma_fp16(oc[nt], pal, &vf[hf * 2]);
            }
        }
    }

    // ---- cross-half reduction + out write ----
    float* Ored = (float*)(dsm + AT_ORED);
    if (wnh == 1) {
#pragma unroll
        for (int nt = 0; nt < 8; ++nt) {
            int col = nt * 8 + (lane & 3) * 2;
            *(float2*)&Ored[rl * 66 + col] = make_float2(oc[nt][0], oc[nt][1]);
            *(float2*)&Ored[(rl + 8) * 66 + col] = make_float2(oc[nt][2], oc[nt][3]);
        }
    }
    __syncthreads();
    if (wnh == 0) {
        float* o0 = outp + ((size_t)b * SS + s0 + rl) * DD;
#pragma unroll
        for (int nt = 0; nt < 8; ++nt) {
            int col = nt * 8 + (lane & 3) * 2;
            float2 r0v = *(float2*)&Ored[rl * 66 + col];
            float2 r1v = *(float2*)&Ored[(rl + 8) * 66 + col];
            *(float2*)&o0[col] = make_float2(oc[nt][0] + r0v.x, oc[nt][1] + r0v.y);
            *(float2*)&o0[8 * DD + col] = make_float2(oc[nt][2] + r1v.x, oc[nt][3] + r1v.y);
        }
    }
}

// ======================================================================
extern "C" void kernel_launch(void* const* d_in, const int* in_sizes, int n_in,
                              void* d_out, int out_size) {
    const float* Q  = (const float*)d_in[0];
    const float* K  = (const float*)d_in[1];
    const float* V  = (const float*)d_in[2];
    const float* Ew = (const float*)d_in[3];
    const float* Eb = (const float*)d_in[4];
    const float* Fw = (const float*)d_in[5];
    const float* Fb = (const float*)d_in[6];

    float* outp  = (float*)d_out;
    float* attnp = outp + (size_t)BB * SS * DD;

    cudaFuncSetAttribute(proj_mma, cudaFuncAttributeMaxDynamicSharedMemorySize, 81920);
    cudaFuncSetAttribute(attn_fused, cudaFuncAttributeMaxDynamicSharedMemorySize, AT_SMEM);

    prepack_W<<<dim3(16, 8, 2), 256>>>(Ew, Fw);
    prepack_X<<<dim3(8, 2, BB), 256>>>(K, V);
    proj_mma<<<dim3(8, 2, BB), 256, 81920>>>(Q);
    proj_reduce_atoms<<<dim3(4, 2, BB), 256>>>(Eb, Fb);
    attn_fused<<<dim3(SS / 64, BB), 256, AT_SMEM>>>(Q, attnp, outp);
}

// round 7
// speedup vs baseline: 3.9458x; 1.3388x over previous
#include <cuda_runtime.h>
#include <cuda_bf16.h>
#include <cuda_fp16.h>
#include <cstdint>

#define BB 16
#define SS 4096
#define DD 64
#define KPP 256
#define SCALE 0.125f

// ---------------- device scratch ----------------
__device__ float g_part8[8 * 2 * 16 * 256 * 64]; // [chunk][proj][b][m256][n64] 16MB
// W as single-fp16 A-operand atoms: [proj][chunk8][stage16][8192]
__device__ __half g_WH[2 * 8 * 16 * 8192];
// X as single-fp16 B-operand atoms: [proj][b][chunk8][stage16][2048]
__device__ __half g_XH[2 * 16 * 8 * 16 * 2048];
// Kp/Vp as single fp16 B-operand atoms (validated R6)
__device__ __half g_KpH[BB * 256 * 64];
__device__ __half g_VpH[BB * 256 * 64];

// ---------------- helpers ----------------
__device__ __forceinline__ uint32_t smem_u32(const void* p) {
    uint32_t a;
    asm("{ .reg .u64 t; cvta.to.shared.u64 t, %1; cvt.u32.u64 %0, t; }" : "=r"(a) : "l"(p));
    return a;
}
__device__ __forceinline__ void ldm_x4(uint32_t* r, uint32_t addr) {
    asm volatile("ldmatrix.sync.aligned.m8n8.x4.shared.b16 {%0,%1,%2,%3}, [%4];"
                 : "=r"(r[0]), "=r"(r[1]), "=r"(r[2]), "=r"(r[3]) : "r"(addr));
}
__device__ __forceinline__ void mma_fp16(float* c, const uint32_t* a, const uint32_t* b) {
    asm volatile(
        "mma.sync.aligned.m16n8k16.row.col.f32.f16.f16.f32 "
        "{%0,%1,%2,%3}, {%4,%5,%6,%7}, {%8,%9}, {%0,%1,%2,%3};"
        : "+f"(c[0]), "+f"(c[1]), "+f"(c[2]), "+f"(c[3])
        : "r"(a[0]), "r"(a[1]), "r"(a[2]), "r"(a[3]), "r"(b[0]), "r"(b[1]));
}
__device__ __forceinline__ void sp2h(float x, __half& h, __half& l) {
    h = __float2half(x);
    l = __float2half(x - __half2float(h));
}
__device__ __forceinline__ uint32_t hpk(__half a, __half b) {
    __half2 t = __halves2half2(a, b);
    return *reinterpret_cast<uint32_t*>(&t);
}
__device__ __forceinline__ void splitpackh(float v0, float v1, uint32_t& h, uint32_t& l) {
    __half h0, l0, h1, l1;
    sp2h(v0, h0, l0);
    sp2h(v1, h1, l1);
    h = hpk(h0, h1);
    l = hpk(l0, l1);
}
__device__ __forceinline__ void cpa16(uint32_t dst, const void* src) {
    asm volatile("cp.async.cg.shared.global [%0], [%1], 16;" :: "r"(dst), "l"(src));
}
#define CP_COMMIT asm volatile("cp.async.commit_group;" ::: "memory")
#define CP_WAIT1 asm volatile("cp.async.wait_group 1;" ::: "memory")
#define CP_WAIT0 asm volatile("cp.async.wait_group 0;" ::: "memory")

// ======================================================================
// Kernel 0a: prepack W -> single fp16 A-atoms. grid (16, 8, 2), 256 thr.
// ======================================================================
__global__ __launch_bounds__(256) void prepack_W(const float* __restrict__ Ew,
                                                 const float* __restrict__ Fw) {
    const int st = blockIdx.x, chunk = blockIdx.y, proj = blockIdx.z;
    const int m = threadIdx.x;
    const float* src = (proj ? Fw : Ew) + (size_t)m * SS + chunk * 512 + st * 32;
    const size_t bb = (size_t)((proj * 8 + chunk) * 16 + st) * 8192;

    float4 f[8];
#pragma unroll
    for (int j = 0; j < 8; ++j) f[j] = *(const float4*)(src + j * 4);
#pragma unroll
    for (int kg = 0; kg < 4; ++kg) {
        float v[8] = {f[2 * kg].x, f[2 * kg].y, f[2 * kg].z, f[2 * kg].w,
                      f[2 * kg + 1].x, f[2 * kg + 1].y, f[2 * kg + 1].z, f[2 * kg + 1].w};
        __half h[8];
#pragma unroll
        for (int e = 0; e < 8; ++e) h[e] = __float2half(v[e]);
        size_t off = bb + (size_t)(((m >> 3) * 4 + kg) * 64 + (m & 7) * 8);
        *(uint4*)&g_WH[off] =
            make_uint4(hpk(h[0], h[1]), hpk(h[2], h[3]), hpk(h[4], h[5]), hpk(h[6], h[7]));
    }
}

// ======================================================================
// Kernel 0b: prepack X -> single fp16 B-atoms. grid (8, 2, 16), 256 thr.
// ======================================================================
__global__ __launch_bounds__(256) void prepack_X(const float* __restrict__ Kin,
                                                 const float* __restrict__ Vin) {
    __shared__ __align__(16) float xs[32][68];
    const int tid = threadIdx.x;
    const int chunk = blockIdx.x, proj = blockIdx.y, b = blockIdx.z;
    const float* X = (proj ? Vin : Kin) + ((size_t)b * SS + chunk * 512) * DD;
    const size_t xb0 = (size_t)(((proj * 16 + b) * 8 + chunk) * 16) * 2048;

    const int d = tid & 63, s8 = tid >> 6;
    for (int st = 0; st < 16; ++st) {
#pragma unroll
        for (int i = 0; i < 2; ++i) {
            int slot = tid + 256 * i;
            int r = slot >> 4, c4 = slot & 15;
            float4 v = *(const float4*)&X[((size_t)st * 32 + r) * DD + c4 * 4];
            *(float4*)&xs[r][c4 * 4] = v;
        }
        __syncthreads();
        __half h[8];
#pragma unroll
        for (int e = 0; e < 8; ++e) h[e] = __float2half(xs[s8 * 8 + e][d]);
        size_t off = xb0 + (size_t)st * 2048 + (size_t)(((d >> 3) * 4 + s8) * 64 + (d & 7) * 8);
        *(uint4*)&g_XH[off] =
            make_uint4(hpk(h[0], h[1]), hpk(h[2], h[3]), hpk(h[4], h[5]), hpk(h[6], h[7]));
        __syncthreads();
    }
}

extern __shared__ __align__(1024) char dsm[];

// ======================================================================
// Kernel 1: projections, single-fp16, cp.async double-buffered.
// grid (8, 2, 16), 256 thr, 40KB dyn smem, 2 CTA/SM.
// Per buf (20480 B): A 0..16384, B 16384..20480.
// ======================================================================
__global__ __launch_bounds__(256, 2) void proj_mma() {
    uint32_t smb = smem_u32(dsm);
    const int tid = threadIdx.x, lane = tid & 31, w = tid >> 5;
    const int chunk = blockIdx.x, proj = blockIdx.y, b = blockIdx.z;
    const int wm = w & 3, wn = w >> 2;
    const int b3 = (lane >> 3) & 1, b4 = lane >> 4, r7 = (lane & 7) * 16;

    const uint4* wp0 = (const uint4*)(g_WH + (size_t)((proj * 8 + chunk) * 16) * 8192);
    const uint4* xp0 = (const uint4*)(g_XH + (size_t)(((proj * 16 + b) * 8 + chunk) * 16) * 2048);

    auto issue = [&](int st) {
        uint32_t base = smb + (uint32_t)(st & 1) * 20480u;
        const uint4* wp = wp0 + (size_t)st * 1024;
        const uint4* xp = xp0 + (size_t)st * 256;
#pragma unroll
        for (int i = 0; i < 4; ++i)
            cpa16(base + (uint32_t)(tid + 256 * i) * 16u, wp + tid + 256 * i);
        cpa16(base + 16384u + (uint32_t)tid * 16u, xp + tid);
    };

    float acc[4][4][4];
#pragma unroll
    for (int i = 0; i < 4; ++i)
#pragma unroll
        for (int j = 0; j < 4; ++j)
#pragma unroll
            for (int e = 0; e < 4; ++e) acc[i][j][e] = 0.f;

    issue(0);
    CP_COMMIT;

    for (int st = 0; st < 16; ++st) {
        if (st < 15) {
            issue(st + 1);
            CP_COMMIT;
            CP_WAIT1;
        } else {
            CP_WAIT0;
        }
        __syncthreads();

        const uint32_t bufb = smb + (uint32_t)(st & 1) * 20480u;
        const uint32_t aH = bufb, bH = bufb + 16384u;

#pragma unroll
        for (int kk2 = 0; kk2 < 2; ++kk2) {
            uint32_t af[4][4], bv[2][4];
#pragma unroll
            for (int mt = 0; mt < 4; ++mt) {
                uint32_t o = (uint32_t)(((wm * 8 + mt * 2 + b3) * 4 + kk2 * 2 + b4) * 128 + r7);
                ldm_x4(af[mt], aH + o);
            }
#pragma unroll
            for (int nt2 = 0; nt2 < 2; ++nt2) {
                uint32_t o = (uint32_t)(((wn * 4 + nt2 * 2 + b4) * 4 + kk2 * 2 + b3) * 128 + r7);
                ldm_x4(bv[nt2], bH + o);
            }
#pragma unroll
            for (int mt = 0; mt < 4; ++mt)
#pragma unroll
                for (int nt2 = 0; nt2 < 2; ++nt2)
#pragma unroll
                    for (int hf = 0; hf < 2; ++hf)
                        mma_fp16(acc[mt][nt2 * 2 + hf], af[mt], &bv[nt2][hf * 2]);
        }
        __syncthreads();
    }

    float* dst = g_part8 + ((size_t)(chunk * 2 + proj) * 16 + b) * 16384;
    const int row = lane >> 2, q2 = (lane & 3) * 2;
#pragma unroll
    for (int mt = 0; mt < 4; ++mt)
#pragma unroll
        for (int nt = 0; nt < 4; ++nt) {
            int m = wm * 64 + mt * 16 + row;
            int n = wn * 32 + nt * 8 + q2;
            *(float2*)&dst[(size_t)m * 64 + n] = make_float2(acc[mt][nt][0], acc[mt][nt][1]);
            *(float2*)&dst[(size_t)(m + 8) * 64 + n] = make_float2(acc[mt][nt][2], acc[mt][nt][3]);
        }
}

// ======================================================================
// Kernel 2: reduce v2 (2x grid). grid (8 kpblk32, 2 proj, 16 b), 256 thr.
// Tile [32 kp][64 d]; emits single fp16 atoms.
// ======================================================================
__global__ __launch_bounds__(256) void proj_reduce_atoms(const float* __restrict__ Eb,
                                                         const float* __restrict__ Fb) {
    __shared__ float tile[32][65];
    const int tid = threadIdx.x;
    const int kpblk = blockIdx.x, p = blockIdx.y, b = blockIdx.z;

    float4 acc[2] = {make_float4(0, 0, 0, 0), make_float4(0, 0, 0, 0)};
#pragma unroll
    for (int c = 0; c < 8; ++c) {
        const float* src = g_part8 + ((size_t)(c * 2 + p) * 16 + b) * 16384 + (size_t)kpblk * 2048;
#pragma unroll
        for (int i = 0; i < 2; ++i) {
            int slot = tid + 256 * i;
            float4 v = *(const float4*)&src[(slot >> 4) * 64 + (slot & 15) * 4];
            acc[i].x += v.x; acc[i].y += v.y; acc[i].z += v.z; acc[i].w += v.w;
        }
    }
    const float* bias = p ? Fb : Eb;
#pragma unroll
    for (int i = 0; i < 2; ++i) {
        int slot = tid + 256 * i;
        int r = slot >> 4, c4 = slot & 15;
        float bv = bias[kpblk * 32 + r];
        tile[r][c4 * 4 + 0] = acc[i].x + bv;
        tile[r][c4 * 4 + 1] = acc[i].y + bv;
        tile[r][c4 * 4 + 2] = acc[i].z + bv;
        tile[r][c4 * 4 + 3] = acc[i].w + bv;
    }
    __syncthreads();

    const int a = tid >> 3, rr = tid & 7;
    if (p == 0) {
        // Kp atoms: kp8 = kpblk*4 + g1 (g1 0..3), d8 = g2 (0..7); entry (kp&7)*8+(d&7)
        const int g1 = a >> 3, g2 = a & 7;
        size_t gbase = (size_t)b * 16384 + (size_t)(((kpblk * 4 + g1) * 8 + g2)) * 64;
        __half h[8];
#pragma unroll
        for (int j = 0; j < 8; ++j) h[j] = __float2half(tile[g1 * 8 + rr][g2 * 8 + j]);
        *(uint4*)&g_KpH[gbase + rr * 8] =
            make_uint4(hpk(h[0], h[1]), hpk(h[2], h[3]), hpk(h[4], h[5]), hpk(h[6], h[7]));
    } else {
        // Vp atoms: d8 = g1 (0..7), kp8 = kpblk*4 + g2 (g2 0..3); entry (d&7)*8+(kp&7)
        const int g1 = a >> 2, g2 = a & 3;
        size_t gbase = (size_t)b * 16384 + (size_t)((g1 * 32 + kpblk * 4 + g2)) * 64;
        __half h[8];
#pragma unroll
        for (int j = 0; j < 8; ++j) h[j] = __float2half(tile[g2 * 8 + j][g1 * 8 + rr]);
        *(uint4*)&g_VpH[gbase + rr * 8] =
            make_uint4(hpk(h[0], h[1]), hpk(h[2], h[3]), hpk(h[4], h[5]), hpk(h[6], h[7]));
    }
}

// ======================================================================
// Kernel 3: fused attention, 2-term fp16 (unchanged R6, validated).
// ======================================================================
#define AT_QHI 0
#define AT_QLO 8192
#define AT_KP 16384
#define AT_VP 49152
#define AT_ORED 81920
#define AT_MAX 98816
#define AT_SUM 99328
#define AT_SMEM 99840

__global__ __launch_bounds__(256, 2) void attn_fused(const float* __restrict__ Q,
                                                     float* __restrict__ attnp,
                                                     float* __restrict__ outp) {
    uint32_t smb = smem_u32(dsm);
    const int tid = threadIdx.x, lane = tid & 31, w = tid >> 5;
    const int b = blockIdx.y, s0 = blockIdx.x * 64;

    {
        const uint4* kh = (const uint4*)(g_KpH + (size_t)b * 16384);
        const uint4* vh = (const uint4*)(g_VpH + (size_t)b * 16384);
#pragma unroll
        for (int i = 0; i < 8; ++i) {
            uint32_t s = (uint32_t)(tid + 256 * i);
            cpa16(smb + AT_KP + s * 16, kh + s);
            cpa16(smb + AT_VP + s * 16, vh + s);
        }
        CP_COMMIT;
    }
    {
        const float* Qb = Q + ((size_t)b * SS + s0) * DD;
        __half* qh = (__half*)(dsm + AT_QHI);
        __half* ql = (__half*)(dsm + AT_QLO);
#pragma unroll
        for (int i = 0; i < 4; ++i) {
            int slot = tid + 256 * i;
            int r = slot >> 4, d4 = slot & 15;
            float4 v = *(const float4*)&Qb[(size_t)r * DD + d4 * 4];
            __half h0, h1, h2, h3, l0, l1, l2, l3;
            sp2h(v.x * SCALE, h0, l0);
            sp2h(v.y * SCALE, h1, l1);
            sp2h(v.z * SCALE, h2, l2);
            sp2h(v.w * SCALE, h3, l3);
            int off = ((r >> 3) * 8 + (d4 >> 1)) * 64 + (r & 7) * 8 + (d4 & 1) * 4;
            *(uint2*)&qh[off] = make_uint2(hpk(h0, h1), hpk(h2, h3));
            *(uint2*)&ql[off] = make_uint2(hpk(l0, l1), hpk(l2, l3));
        }
    }
    CP_WAIT0;
    __syncthreads();

    const int wm = w >> 1, wnh = w & 1;
    const int b3 = (lane >> 3) & 1, b4 = lane >> 4, r7 = (lane & 7) * 16;
    const uint32_t qhi = smb + AT_QHI, qlo = smb + AT_QLO;
    const uint32_t kp = smb + AT_KP, vp = smb + AT_VP;

    float c[16][4];
#pragma unroll
    for (int i = 0; i < 16; ++i)
#pragma unroll
        for (int e = 0; e < 4; ++e) c[i][e] = 0.f;

#pragma unroll
    for (int kk = 0; kk < 4; ++kk) {
        uint32_t ah[4], al[4];
        uint32_t oA = (uint32_t)(((wm * 2 + b3) * 8 + kk * 2 + b4) * 128 + r7);
        ldm_x4(ah, qhi + oA);
        ldm_x4(al, qlo + oA);
#pragma unroll
        for (int nt2 = 0; nt2 < 8; ++nt2) {
            uint32_t bf[4];
            uint32_t oB = (uint32_t)(((wnh * 16 + nt2 * 2 + b4) * 8 + kk * 2 + b3) * 128 + r7);
            ldm_x4(bf, kp + oB);
#pragma unroll
            for (int hf = 0; hf < 2; ++hf) {
                int nt = nt2 * 2 + hf;
                mma_fp16(c[nt], ah, &bf[hf * 2]);
                mma_fp16(c[nt], al, &bf[hf * 2]);
            }
        }
    }

    const int rl = wm * 16 + (lane >> 2);
    float* smax = (float*)(dsm + AT_MAX);
    float* ssum = (float*)(dsm + AT_SUM);

    float m0 = -1e30f, m1 = -1e30f;
#pragma unroll
    for (int nt = 0; nt < 16; ++nt) {
        m0 = fmaxf(m0, fmaxf(c[nt][0], c[nt][1]));
        m1 = fmaxf(m1, fmaxf(c[nt][2], c[nt][3]));
    }
#pragma unroll
    for (int off = 1; off <= 2; off <<= 1) {
        m0 = fmaxf(m0, __shfl_xor_sync(0xffffffffu, m0, off));
        m1 = fmaxf(m1, __shfl_xor_sync(0xffffffffu, m1, off));
    }
    if ((lane & 3) == 0) {
        smax[wnh * 64 + rl] = m0;
        smax[wnh * 64 + rl + 8] = m1;
    }
    __syncthreads();
    m0 = fmaxf(m0, smax[(wnh ^ 1) * 64 + rl]);
    m1 = fmaxf(m1, smax[(wnh ^ 1) * 64 + rl + 8]);

    float s0a = 0.f, s1a = 0.f;
#pragma unroll
    for (int nt = 0; nt < 16; ++nt) {
        c[nt][0] = __expf(c[nt][0] - m0);
        c[nt][1] = __expf(c[nt][1] - m0);
        c[nt][2] = __expf(c[nt][2] - m1);
        c[nt][3] = __expf(c[nt][3] - m1);
        s0a += c[nt][0] + c[nt][1];
        s1a += c[nt][2] + c[nt][3];
    }
#pragma unroll
    for (int off = 1; off <= 2; off <<= 1) {
        s0a += __shfl_xor_sync(0xffffffffu, s0a, off);
        s1a += __shfl_xor_sync(0xffffffffu, s1a, off);
    }
    if ((lane & 3) == 0) {
        ssum[wnh * 64 + rl] = s0a;
        ssum[wnh * 64 + rl + 8] = s1a;
    }
    __syncthreads();
    float inv0 = 1.f / (s0a + ssum[(wnh ^ 1) * 64 + rl]);
    float inv1 = 1.f / (s1a + ssum[(wnh ^ 1) * 64 + rl + 8]);

    float* abase = attnp + ((size_t)b * SS + s0 + rl) * KPP + wnh * 128 + (lane & 3) * 2;
#pragma unroll
    for (int nt = 0; nt < 16; ++nt) {
        c[nt][0] *= inv0;
        c[nt][1] *= inv0;
        c[nt][2] *= inv1;
        c[nt][3] *= inv1;
        *(float2*)&abase[nt * 8] = make_float2(c[nt][0], c[nt][1]);
        *(float2*)&abase[8 * KPP + nt * 8] = make_float2(c[nt][2], c[nt][3]);
    }

    float oc[8][4];
#pragma unroll
    for (int i = 0; i < 8; ++i)
#pragma unroll
        for (int e = 0; e < 4; ++e) oc[i][e] = 0.f;

#pragma unroll
    for (int t2 = 0; t2 < 8; ++t2) {
        uint32_t pah[4], pal[4];
        splitpackh(c[2 * t2][0], c[2 * t2][1], pah[0], pal[0]);
        splitpackh(c[2 * t2][2], c[2 * t2][3], pah[1], pal[1]);
        splitpackh(c[2 * t2 + 1][0], c[2 * t2 + 1][1], pah[2], pal[2]);
        splitpackh(c[2 * t2 + 1][2], c[2 * t2 + 1][3], pah[3], pal[3]);
#pragma unroll
        for (int nt2 = 0; nt2 < 4; ++nt2) {
            uint32_t vf[4];
            uint32_t oV = (uint32_t)(((nt2 * 2 + b4) * 32 + wnh * 16 + t2 * 2 + b3) * 128 + r7);
            ldm_x4(vf, vp + oV);
#pragma unroll
            for (int hf = 0; hf < 2; ++hf) {
                int nt = nt2 * 2 + hf;
                mma_fp16(oc[nt], pah, &vf[hf * 2]);
                mma_fp16(oc[nt], pal, &vf[hf * 2]);
            }
        }
    }

    float* Ored = (float*)(dsm + AT_ORED);
    if (wnh == 1) {
#pragma unroll
        for (int nt = 0; nt < 8; ++nt) {
            int col = nt * 8 + (lane & 3) * 2;
            *(float2*)&Ored[rl * 66 + col] = make_float2(oc[nt][0], oc[nt][1]);
            *(float2*)&Ored[(rl + 8) * 66 + col] = make_float2(oc[nt][2], oc[nt][3]);
        }
    }
    __syncthreads();
    if (wnh == 0) {
        float* o0 = outp + ((size_t)b * SS + s0 + rl) * DD;
#pragma unroll
        for (int nt = 0; nt < 8; ++nt) {
            int col = nt * 8 + (lane & 3) * 2;
            float2 r0v = *(float2*)&Ored[rl * 66 + col];
            float2 r1v = *(float2*)&Ored[(rl + 8) * 66 + col];
            *(float2*)&o0[col] = make_float2(oc[nt][0] + r0v.x, oc[nt][1] + r0v.y);
            *(float2*)&o0[8 * DD + col] = make_float2(oc[nt][2] + r1v.x, oc[nt][3] + r1v.y);
        }
    }
}

// ======================================================================
extern "C" void kernel_launch(void* const* d_in, const int* in_sizes, int n_in,
                              void* d_out, int out_size) {
    const float* Q  = (const float*)d_in[0];
    const float* K  = (const float*)d_in[1];
    const float* V  = (const float*)d_in[2];
    const float* Ew = (const float*)d_in[3];
    const float* Eb = (const float*)d_in[4];
    const float* Fw = (const float*)d_in[5];
    const float* Fb = (const float*)d_in[6];

    float* outp  = (float*)d_out;
    float* attnp = outp + (size_t)BB * SS * DD;

    cudaFuncSetAttribute(proj_mma, cudaFuncAttributeMaxDynamicSharedMemorySize, 40960);
    cudaFuncSetAttribute(attn_fused, cudaFuncAttributeMaxDynamicSharedMemorySize, AT_SMEM);

    prepack_W<<<dim3(16, 8, 2), 256>>>(Ew, Fw);
    prepack_X<<<dim3(8, 2, BB), 256>>>(K, V);
    proj_mma<<<dim3(8, 2, BB), 256, 40960>>>();
    proj_reduce_atoms<<<dim3(8, 2, BB), 256>>>(Eb, Fb);
    attn_fused<<<dim3(SS / 64, BB), 256, AT_SMEM>>>(Q, attnp, outp);
}

// round 8
// speedup vs baseline: 4.3799x; 1.1100x over previous
#include <cuda_runtime.h>
#include <cuda_fp16.h>
#include <cstdint>

#define BB 16
#define SS 4096
#define DD 64
#define KPP 256
#define SCALE 0.125f

// ---------------- device scratch ----------------
__device__ float g_part8[8 * 2 * 16 * 256 * 64]; // [chunk][proj][b][m256][n64] 16MB
__device__ __half g_WH[2 * 8 * 16 * 8192];       // W A-atoms [proj][chunk][stage][8192]
__device__ __half g_XH[2 * 16 * 8 * 16 * 2048];  // X B-atoms [proj][b][chunk][stage][2048]
__device__ __half g_KpH[BB * 256 * 64];          // Kp B-atoms (n=kp, k=d)
__device__ __half g_VpH[BB * 256 * 64];          // Vp B-atoms (n=d, k=kp)

// ---------------- helpers ----------------
__device__ __forceinline__ uint32_t smem_u32(const void* p) {
    uint32_t a;
    asm("{ .reg .u64 t; cvta.to.shared.u64 t, %1; cvt.u32.u64 %0, t; }" : "=r"(a) : "l"(p));
    return a;
}
__device__ __forceinline__ void ldm_x4(uint32_t* r, uint32_t addr) {
    asm volatile("ldmatrix.sync.aligned.m8n8.x4.shared.b16 {%0,%1,%2,%3}, [%4];"
                 : "=r"(r[0]), "=r"(r[1]), "=r"(r[2]), "=r"(r[3]) : "r"(addr));
}
__device__ __forceinline__ void mma_fp16(float* c, const uint32_t* a, const uint32_t* b) {
    asm volatile(
        "mma.sync.aligned.m16n8k16.row.col.f32.f16.f16.f32 "
        "{%0,%1,%2,%3}, {%4,%5,%6,%7}, {%8,%9}, {%0,%1,%2,%3};"
        : "+f"(c[0]), "+f"(c[1]), "+f"(c[2]), "+f"(c[3])
        : "r"(a[0]), "r"(a[1]), "r"(a[2]), "r"(a[3]), "r"(b[0]), "r"(b[1]));
}
__device__ __forceinline__ uint32_t hpk(__half a, __half b) {
    __half2 t = __halves2half2(a, b);
    return *reinterpret_cast<uint32_t*>(&t);
}
__device__ __forceinline__ uint32_t hpk2(float a, float b) {
    __half2 t = __floats2half2_rn(a, b);
    return *reinterpret_cast<uint32_t*>(&t);
}
__device__ __forceinline__ void cpa16(uint32_t dst, const void* src) {
    asm volatile("cp.async.cg.shared.global [%0], [%1], 16;" :: "r"(dst), "l"(src));
}
#define CP_COMMIT asm volatile("cp.async.commit_group;" ::: "memory")
#define CP_WAIT1 asm volatile("cp.async.wait_group 1;" ::: "memory")
#define CP_WAIT0 asm volatile("cp.async.wait_group 0;" ::: "memory")

// ======================================================================
// Kernel 0a: prepack W -> fp16 A-atoms. grid (16, 8, 2), 256 thr.
// ======================================================================
__global__ __launch_bounds__(256) void prepack_W(const float* __restrict__ Ew,
                                                 const float* __restrict__ Fw) {
    const int st = blockIdx.x, chunk = blockIdx.y, proj = blockIdx.z;
    const int m = threadIdx.x;
    const float* src = (proj ? Fw : Ew) + (size_t)m * SS + chunk * 512 + st * 32;
    const size_t bb = (size_t)((proj * 8 + chunk) * 16 + st) * 8192;

    float4 f[8];
#pragma unroll
    for (int j = 0; j < 8; ++j) f[j] = *(const float4*)(src + j * 4);
#pragma unroll
    for (int kg = 0; kg < 4; ++kg) {
        float4 a = f[2 * kg], b = f[2 * kg + 1];
        size_t off = bb + (size_t)(((m >> 3) * 4 + kg) * 64 + (m & 7) * 8);
        *(uint4*)&g_WH[off] =
            make_uint4(hpk2(a.x, a.y), hpk2(a.z, a.w), hpk2(b.x, b.y), hpk2(b.z, b.w));
    }
}

// ======================================================================
// Kernel 0b: prepack X -> fp16 B-atoms, direct (no smem). grid (8,2,16), 256 thr.
// thread: d = tid&63, sg = tid>>6.
// ======================================================================
__global__ __launch_bounds__(256) void prepack_X(const float* __restrict__ Kin,
                                                 const float* __restrict__ Vin) {
    const int tid = threadIdx.x;
    const int chunk = blockIdx.x, proj = blockIdx.y, b = blockIdx.z;
    const float* X = (proj ? Vin : Kin) + ((size_t)b * SS + chunk * 512) * DD;
    const size_t xb0 = (size_t)(((proj * 16 + b) * 8 + chunk) * 16) * 2048;

    const int d = tid & 63, sg = tid >> 6;
    const size_t soff = (size_t)(((d >> 3) * 4 + sg) * 64 + (d & 7) * 8);
#pragma unroll 4
    for (int st = 0; st < 16; ++st) {
        const float* col = X + (size_t)(st * 32 + sg * 8) * DD + d;
        float v[8];
#pragma unroll
        for (int e = 0; e < 8; ++e) v[e] = col[e * DD];
        *(uint4*)&g_XH[xb0 + (size_t)st * 2048 + soff] =
            make_uint4(hpk2(v[0], v[1]), hpk2(v[2], v[3]), hpk2(v[4], v[5]), hpk2(v[6], v[7]));
    }
}

extern __shared__ __align__(1024) char dsm[];

// ======================================================================
// Kernel 1: projections, single-fp16, cp.async double-buffered (R7 validated).
// ======================================================================
__global__ __launch_bounds__(256, 2) void proj_mma() {
    uint32_t smb = smem_u32(dsm);
    const int tid = threadIdx.x, lane = tid & 31, w = tid >> 5;
    const int chunk = blockIdx.x, proj = blockIdx.y, b = blockIdx.z;
    const int wm = w & 3, wn = w >> 2;
    const int b3 = (lane >> 3) & 1, b4 = lane >> 4, r7 = (lane & 7) * 16;

    const uint4* wp0 = (const uint4*)(g_WH + (size_t)((proj * 8 + chunk) * 16) * 8192);
    const uint4* xp0 = (const uint4*)(g_XH + (size_t)(((proj * 16 + b) * 8 + chunk) * 16) * 2048);

    auto issue = [&](int st) {
        uint32_t base = smb + (uint32_t)(st & 1) * 20480u;
        const uint4* wp = wp0 + (size_t)st * 1024;
        const uint4* xp = xp0 + (size_t)st * 256;
#pragma unroll
        for (int i = 0; i < 4; ++i)
            cpa16(base + (uint32_t)(tid + 256 * i) * 16u, wp + tid + 256 * i);
        cpa16(base + 16384u + (uint32_t)tid * 16u, xp + tid);
    };

    float acc[4][4][4];
#pragma unroll
    for (int i = 0; i < 4; ++i)
#pragma unroll
        for (int j = 0; j < 4; ++j)
#pragma unroll
            for (int e = 0; e < 4; ++e) acc[i][j][e] = 0.f;

    issue(0);
    CP_COMMIT;

    for (int st = 0; st < 16; ++st) {
        if (st < 15) {
            issue(st + 1);
            CP_COMMIT;
            CP_WAIT1;
        } else {
            CP_WAIT0;
        }
        __syncthreads();

        const uint32_t bufb = smb + (uint32_t)(st & 1) * 20480u;
        const uint32_t aH = bufb, bH = bufb + 16384u;

#pragma unroll
        for (int kk2 = 0; kk2 < 2; ++kk2) {
            uint32_t af[4][4], bv[2][4];
#pragma unroll
            for (int mt = 0; mt < 4; ++mt) {
                uint32_t o = (uint32_t)(((wm * 8 + mt * 2 + b3) * 4 + kk2 * 2 + b4) * 128 + r7);
                ldm_x4(af[mt], aH + o);
            }
#pragma unroll
            for (int nt2 = 0; nt2 < 2; ++nt2) {
                uint32_t o = (uint32_t)(((wn * 4 + nt2 * 2 + b4) * 4 + kk2 * 2 + b3) * 128 + r7);
                ldm_x4(bv[nt2], bH + o);
            }
#pragma unroll
            for (int mt = 0; mt < 4; ++mt)
#pragma unroll
                for (int nt2 = 0; nt2 < 2; ++nt2)
#pragma unroll
                    for (int hf = 0; hf < 2; ++hf)
                        mma_fp16(acc[mt][nt2 * 2 + hf], af[mt], &bv[nt2][hf * 2]);
        }
        __syncthreads();
    }

    float* dst = g_part8 + ((size_t)(chunk * 2 + proj) * 16 + b) * 16384;
    const int row = lane >> 2, q2 = (lane & 3) * 2;
#pragma unroll
    for (int mt = 0; mt < 4; ++mt)
#pragma unroll
        for (int nt = 0; nt < 4; ++nt) {
            int m = wm * 64 + mt * 16 + row;
            int n = wn * 32 + nt * 8 + q2;
            *(float2*)&dst[(size_t)m * 64 + n] = make_float2(acc[mt][nt][0], acc[mt][nt][1]);
            *(float2*)&dst[(size_t)(m + 8) * 64 + n] = make_float2(acc[mt][nt][2], acc[mt][nt][3]);
        }
}

// ======================================================================
// Kernel 2: reduce v3, 512 CTAs. grid (16 = kpblk8*2 + dhalf, 2, 16), 256 thr.
// Tile [32 kp][32 d].
// ======================================================================
__global__ __launch_bounds__(256) void proj_reduce_atoms(const float* __restrict__ Eb,
                                                         const float* __restrict__ Fb) {
    __shared__ float tile[32][33];
    const int tid = threadIdx.x;
    const int kpblk = blockIdx.x >> 1, dhalf = blockIdx.x & 1;
    const int p = blockIdx.y, b = blockIdx.z;

    const int r = tid >> 3, c4 = tid & 7; // kp row 0..31, d quad 0..7
    float4 acc = make_float4(0.f, 0.f, 0.f, 0.f);
    const size_t eoff = (size_t)(kpblk * 32 + r) * 64 + dhalf * 32 + c4 * 4;
#pragma unroll
    for (int c = 0; c < 8; ++c) {
        float4 v = *(const float4*)&g_part8[((size_t)(c * 2 + p) * 16 + b) * 16384 + eoff];
        acc.x += v.x; acc.y += v.y; acc.z += v.z; acc.w += v.w;
    }
    const float* bias = p ? Fb : Eb;
    float bv = bias[kpblk * 32 + r];
    tile[r][c4 * 4 + 0] = acc.x + bv;
    tile[r][c4 * 4 + 1] = acc.y + bv;
    tile[r][c4 * 4 + 2] = acc.z + bv;
    tile[r][c4 * 4 + 3] = acc.w + bv;
    __syncthreads();

    if (tid < 128) {
        const int atom = tid >> 3, rr = tid & 7;
        __half h[8];
        if (p == 0) {
            const int g1 = atom >> 2, g2 = atom & 3; // kp8, d8
#pragma unroll
            for (int j = 0; j < 8; ++j) h[j] = __float2half(tile[g1 * 8 + rr][g2 * 8 + j]);
            size_t gbase =
                (size_t)b * 16384 + (size_t)(((kpblk * 4 + g1) * 8 + dhalf * 4 + g2)) * 64;
            *(uint4*)&g_KpH[gbase + rr * 8] =
                make_uint4(hpk(h[0], h[1]), hpk(h[2], h[3]), hpk(h[4], h[5]), hpk(h[6], h[7]));
        } else {
            const int gd = atom >> 2, gk = atom & 3; // d8, kp8
#pragma unroll
            for (int j = 0; j < 8; ++j) h[j] = __float2half(tile[gk * 8 + j][gd * 8 + rr]);
            size_t gbase =
                (size_t)b * 16384 + (size_t)(((dhalf * 4 + gd) * 32 + kpblk * 4 + gk)) * 64;
            *(uint4*)&g_VpH[gbase + rr * 8] =
                make_uint4(hpk(h[0], h[1]), hpk(h[2], h[3]), hpk(h[4], h[5]), hpk(h[6], h[7]));
        }
    }
}

// ======================================================================
// Kernel 3: fused attention, single-fp16 everywhere. 91.6KB smem, 2 CTA/SM.
// ======================================================================
#define AT_Q 0
#define AT_KP 8192
#define AT_VP 40960
#define AT_ORED 73728
#define AT_MAX 90624
#define AT_SUM 91136
#define AT_SMEM 91648

__global__ __launch_bounds__(256, 2) void attn_fused(const float* __restrict__ Q,
                                                     float* __restrict__ attnp,
                                                     float* __restrict__ outp) {
    uint32_t smb = smem_u32(dsm);
    const int tid = threadIdx.x, lane = tid & 31, w = tid >> 5;
    const int b = blockIdx.y, s0 = blockIdx.x * 64;

    // ---- stage Kp/Vp fp16 atoms via cp.async ----
    {
        const uint4* kh = (const uint4*)(g_KpH + (size_t)b * 16384);
        const uint4* vh = (const uint4*)(g_VpH + (size_t)b * 16384);
#pragma unroll
        for (int i = 0; i < 8; ++i) {
            uint32_t s = (uint32_t)(tid + 256 * i);
            cpa16(smb + AT_KP + s * 16, kh + s);
            cpa16(smb + AT_VP + s * 16, vh + s);
        }
        CP_COMMIT;
    }
    // ---- build Q fp16 A-atoms (scale folded) while copies fly ----
    {
        const float* Qb = Q + ((size_t)b * SS + s0) * DD;
        __half* qa = (__half*)(dsm + AT_Q);
#pragma unroll
        for (int i = 0; i < 4; ++i) {
            int slot = tid + 256 * i;
            int r = slot >> 4, d4 = slot & 15;
            float4 v = *(const float4*)&Qb[(size_t)r * DD + d4 * 4];
            int off = ((r >> 3) * 8 + (d4 >> 1)) * 64 + (r & 7) * 8 + (d4 & 1) * 4;
            *(uint2*)&qa[off] =
                make_uint2(hpk2(v.x * SCALE, v.y * SCALE), hpk2(v.z * SCALE, v.w * SCALE));
        }
    }
    CP_WAIT0;
    __syncthreads();

    const int wm = w >> 1, wnh = w & 1;
    const int b3 = (lane >> 3) & 1, b4 = lane >> 4, r7 = (lane & 7) * 16;
    const uint32_t qa = smb + AT_Q;
    const uint32_t kp = smb + AT_KP, vp = smb + AT_VP;

    // ---- scores: Q(fp16) @ Kp(fp16) ----
    float c[16][4];
#pragma unroll
    for (int i = 0; i < 16; ++i)
#pragma unroll
        for (int e = 0; e < 4; ++e) c[i][e] = 0.f;

#pragma unroll
    for (int kk = 0; kk < 4; ++kk) {
        uint32_t aq[4];
        uint32_t oA = (uint32_t)(((wm * 2 + b3) * 8 + kk * 2 + b4) * 128 + r7);
        ldm_x4(aq, qa + oA);
#pragma unroll
        for (int nt2 = 0; nt2 < 8; ++nt2) {
            uint32_t bf[4];
            uint32_t oB = (uint32_t)(((wnh * 16 + nt2 * 2 + b4) * 8 + kk * 2 + b3) * 128 + r7);
            ldm_x4(bf, kp + oB);
            mma_fp16(c[nt2 * 2], aq, &bf[0]);
            mma_fp16(c[nt2 * 2 + 1], aq, &bf[2]);
        }
    }

    // ---- softmax over 256 (two warp-halves joined via smem) ----
    const int rl = wm * 16 + (lane >> 2);
    float* smax = (float*)(dsm + AT_MAX);
    float* ssum = (float*)(dsm + AT_SUM);

    float m0 = -1e30f, m1 = -1e30f;
#pragma unroll
    for (int nt = 0; nt < 16; ++nt) {
        m0 = fmaxf(m0, fmaxf(c[nt][0], c[nt][1]));
        m1 = fmaxf(m1, fmaxf(c[nt][2], c[nt][3]));
    }
#pragma unroll
    for (int off = 1; off <= 2; off <<= 1) {
        m0 = fmaxf(m0, __shfl_xor_sync(0xffffffffu, m0, off));
        m1 = fmaxf(m1, __shfl_xor_sync(0xffffffffu, m1, off));
    }
    if ((lane & 3) == 0) {
        smax[wnh * 64 + rl] = m0;
        smax[wnh * 64 + rl + 8] = m1;
    }
    __syncthreads();
    m0 = fmaxf(m0, smax[(wnh ^ 1) * 64 + rl]);
    m1 = fmaxf(m1, smax[(wnh ^ 1) * 64 + rl + 8]);

    float s0a = 0.f, s1a = 0.f;
#pragma unroll
    for (int nt = 0; nt < 16; ++nt) {
        c[nt][0] = __expf(c[nt][0] - m0);
        c[nt][1] = __expf(c[nt][1] - m0);
        c[nt][2] = __expf(c[nt][2] - m1);
        c[nt][3] = __expf(c[nt][3] - m1);
        s0a += c[nt][0] + c[nt][1];
        s1a += c[nt][2] + c[nt][3];
    }
#pragma unroll
    for (int off = 1; off <= 2; off <<= 1) {
        s0a += __shfl_xor_sync(0xffffffffu, s0a, off);
        s1a += __shfl_xor_sync(0xffffffffu, s1a, off);
    }
    if ((lane & 3) == 0) {
        ssum[wnh * 64 + rl] = s0a;
        ssum[wnh * 64 + rl + 8] = s1a;
    }
    __syncthreads();
    float inv0 = 1.f / (s0a + ssum[(wnh ^ 1) * 64 + rl]);
    float inv1 = 1.f / (s1a + ssum[(wnh ^ 1) * 64 + rl + 8]);

    // ---- scale probs + write attn ----
    float* abase = attnp + ((size_t)b * SS + s0 + rl) * KPP + wnh * 128 + (lane & 3) * 2;
#pragma unroll
    for (int nt = 0; nt < 16; ++nt) {
        c[nt][0] *= inv0;
        c[nt][1] *= inv0;
        c[nt][2] *= inv1;
        c[nt][3] *= inv1;
        *(float2*)&abase[nt * 8] = make_float2(c[nt][0], c[nt][1]);
        *(float2*)&abase[8 * KPP + nt * 8] = make_float2(c[nt][2], c[nt][3]);
    }

    // ---- out GEMM: P(fp16 frag) @ Vp(fp16), k-half per warp ----
    float oc[8][4];
#pragma unroll
    for (int i = 0; i < 8; ++i)
#pragma unroll
        for (int e = 0; e < 4; ++e) oc[i][e] = 0.f;

#pragma unroll
    for (int t2 = 0; t2 < 8; ++t2) {
        uint32_t pa[4];
        pa[0] = hpk2(c[2 * t2][0], c[2 * t2][1]);
        pa[1] = hpk2(c[2 * t2][2], c[2 * t2][3]);
        pa[2] = hpk2(c[2 * t2 + 1][0], c[2 * t2 + 1][1]);
        pa[3] = hpk2(c[2 * t2 + 1][2], c[2 * t2 + 1][3]);
#pragma unroll
        for (int nt2 = 0; nt2 < 4; ++nt2) {
            uint32_t vf[4];
            uint32_t oV = (uint32_t)(((nt2 * 2 + b4) * 32 + wnh * 16 + t2 * 2 + b3) * 128 + r7);
            ldm_x4(vf, vp + oV);
            mma_fp16(oc[nt2 * 2], pa, &vf[0]);
            mma_fp16(oc[nt2 * 2 + 1], pa, &vf[2]);
        }
    }

    // ---- cross-half reduction + out write ----
    float* Ored = (float*)(dsm + AT_ORED);
    if (wnh == 1) {
#pragma unroll
        for (int nt = 0; nt < 8; ++nt) {
            int col = nt * 8 + (lane & 3) * 2;
            *(float2*)&Ored[rl * 66 + col] = make_float2(oc[nt][0], oc[nt][1]);
            *(float2*)&Ored[(rl + 8) * 66 + col] = make_float2(oc[nt][2], oc[nt][3]);
        }
    }
    __syncthreads();
    if (wnh == 0) {
        float* o0 = outp + ((size_t)b * SS + s0 + rl) * DD;
#pragma unroll
        for (int nt = 0; nt < 8; ++nt) {
            int col = nt * 8 + (lane & 3) * 2;
            float2 r0v = *(float2*)&Ored[rl * 66 + col];
            float2 r1v = *(float2*)&Ored[(rl + 8) * 66 + col];
            *(float2*)&o0[col] = make_float2(oc[nt][0] + r0v.x, oc[nt][1] + r0v.y);
            *(float2*)&o0[8 * DD + col] = make_float2(oc[nt][2] + r1v.x, oc[nt][3] + r1v.y);
        }
    }
}

// ======================================================================
extern "C" void kernel_launch(void* const* d_in, const int* in_sizes, int n_in,
                              void* d_out, int out_size) {
    const float* Q  = (const float*)d_in[0];
    const float* K  = (const float*)d_in[1];
    const float* V  = (const float*)d_in[2];
    const float* Ew = (const float*)d_in[3];
    const float* Eb = (const float*)d_in[4];
    const float* Fw = (const float*)d_in[5];
    const float* Fb = (const float*)d_in[6];

    float* outp  = (float*)d_out;
    float* attnp = outp + (size_t)BB * SS * DD;

    cudaFuncSetAttribute(proj_mma, cudaFuncAttributeMaxDynamicSharedMemorySize, 40960);
    cudaFuncSetAttribute(attn_fused, cudaFuncAttributeMaxDynamicSharedMemorySize, AT_SMEM);

    prepack_W<<<dim3(16, 8, 2), 256>>>(Ew, Fw);
    prepack_X<<<dim3(8, 2, BB), 256>>>(K, V);
    proj_mma<<<dim3(8, 2, BB), 256, 40960>>>();
    proj_reduce_atoms<<<dim3(16, 2, BB), 256>>>(Eb, Fb);
    attn_fused<<<dim3(SS / 64, BB), 256, AT_SMEM>>>(Q, attnp, outp);
}